// round 9
// baseline (speedup 1.0000x reference)
#include <cuda_runtime.h>
#include <cuda_fp16.h>
#include <math.h>
#include <stdint.h>

// Problem constants
#define BB   2
#define TT   2048
#define DD   2048
#define NH   16
#define NKV  4
#define HDm  128
#define MROWS (BB*TT)   // 4096

// Scratch
__device__ float g_q[BB*NH*TT*HDm];
__device__ float g_k[BB*NKV*TT*HDm];
__device__ float g_v[BB*NKV*TT*HDm];
__device__ float g_ctx[BB*TT*DD];
__device__ float g_rope[TT*128];       // [t][0..63]=cos, [t][64..127]=sin

// ---------------------------------------------------------------------------
// helpers
// ---------------------------------------------------------------------------
__device__ __forceinline__ uint32_t f2h2(float a, float b) {
    __half2 h = __floats2half2_rn(a, b);
    return *reinterpret_cast<uint32_t*>(&h);
}
__device__ __forceinline__ float rhf(float x) {   // round through fp16
    return __half2float(__float2half_rn(x));
}
__device__ __forceinline__ float ex2(float x) {
    float y; asm("ex2.approx.f32 %0, %1;" : "=f"(y) : "f"(x)); return y;
}
// m16n8k16 fp16 MMA, fp32 accumulate
__device__ __forceinline__ void mma_f16(float c[4],
                                        uint32_t a0, uint32_t a1, uint32_t a2, uint32_t a3,
                                        uint32_t b0, uint32_t b1) {
    asm volatile(
        "mma.sync.aligned.m16n8k16.row.col.f32.f16.f16.f32 "
        "{%0,%1,%2,%3}, {%4,%5,%6,%7}, {%8,%9}, {%0,%1,%2,%3};\n"
        : "+f"(c[0]), "+f"(c[1]), "+f"(c[2]), "+f"(c[3])
        : "r"(a0), "r"(a1), "r"(a2), "r"(a3), "r"(b0), "r"(b1));
}

// ---------------------------------------------------------------------------
// fp16 GEMM core: BM=BN=128, BK=32, 128 threads (4 warps 2x2), warp tile 64x64,
// double-buffered. A smem [m][kpair] stride 20 words; B smem [n][kpair] stride
// 20 words (transposed at staging). All fragment LDS patterns conflict-free.
// ---------------------------------------------------------------------------
#define ASTW 20
#define BSTW 20
#define A_SZW (128 * ASTW)           // 2560 words
#define B_SZW (128 * BSTW)           // 2560 words
#define GBUFW (A_SZW + B_SZW)        // 5120 words
#define GEMM_SMEM_BYTES (2 * GBUFW * 4)   // 40960

// Fused QKV projection: blockIdx.x selects {wq: 0..15, wk: 16..19, wv: 20..23}.
__global__ void __launch_bounds__(128, 2)
tqkv_k(const float* __restrict__ A,
       const float* __restrict__ wq, const float* __restrict__ wk,
       const float* __restrict__ wv,
       float* __restrict__ qo, float* __restrict__ ko, float* __restrict__ vo)
{
    extern __shared__ uint32_t gsm[];

    const int bx = blockIdx.x;
    const float* Bm;
    float* C;
    int N, n0, Hx;
    if (bx < 16)      { Bm = wq; C = qo; N = 2048; n0 = bx * 128;        Hx = 16; }
    else if (bx < 20) { Bm = wk; C = ko; N = 512;  n0 = (bx - 16) * 128; Hx = 4;  }
    else              { Bm = wv; C = vo; N = 512;  n0 = (bx - 20) * 128; Hx = 4;  }
    const int K = DD;

    const int tid = threadIdx.x;
    const int lane = tid & 31;
    const int wid = tid >> 5;
    const int warpM = wid & 1;
    const int warpN = wid >> 1;
    const int m0 = blockIdx.y * 128;

    const int arow = tid >> 3;         // 0..15 (+p*16)
    const int acolf = (tid & 7) * 4;   // global float col group
    const int acolw = (tid & 7) * 2;   // smem word col

    float acc[4][8][4];
#pragma unroll
    for (int i = 0; i < 4; i++)
#pragma unroll
        for (int jj = 0; jj < 8; jj++)
#pragma unroll
            for (int r = 0; r < 4; r++) acc[i][jj][r] = 0.f;

    uint32_t rah[16], rbh[16];
    // prefetch chunk 0
#pragma unroll
    for (int p = 0; p < 8; p++) {
        float4 v = *(const float4*)&A[(long)(m0 + arow + p * 16) * K + acolf];
        rah[2 * p]     = f2h2(v.x, v.y);
        rah[2 * p + 1] = f2h2(v.z, v.w);
    }
#pragma unroll
    for (int kk = 0; kk < 16; kk++) {
        float f0 = Bm[(long)(2 * kk)     * N + n0 + tid];
        float f1 = Bm[(long)(2 * kk + 1) * N + n0 + tid];
        rbh[kk] = f2h2(f0, f1);
    }

    const int NKT = K / 32;
    for (int kt = 0; kt < NKT; kt++) {
        uint32_t* As = gsm + (kt & 1) * GBUFW;
        uint32_t* Bs = As + A_SZW;

#pragma unroll
        for (int p = 0; p < 8; p++) {
            int m = arow + p * 16;
            *(uint2*)&As[m * ASTW + acolw] = make_uint2(rah[2 * p], rah[2 * p + 1]);
        }
#pragma unroll
        for (int s = 0; s < 4; s++)
            *(uint4*)&Bs[tid * BSTW + s * 4] =
                make_uint4(rbh[4 * s], rbh[4 * s + 1], rbh[4 * s + 2], rbh[4 * s + 3]);
        __syncthreads();

        if (kt + 1 < NKT) {
            int k0 = (kt + 1) * 32;
#pragma unroll
            for (int p = 0; p < 8; p++) {
                float4 v = *(const float4*)&A[(long)(m0 + arow + p * 16) * K + k0 + acolf];
                rah[2 * p]     = f2h2(v.x, v.y);
                rah[2 * p + 1] = f2h2(v.z, v.w);
            }
#pragma unroll
            for (int kk = 0; kk < 16; kk++) {
                float f0 = Bm[(long)(k0 + 2 * kk)     * N + n0 + tid];
                float f1 = Bm[(long)(k0 + 2 * kk + 1) * N + n0 + tid];
                rbh[kk] = f2h2(f0, f1);
            }
        }

#pragma unroll
        for (int ks = 0; ks < 2; ks++) {
            const int base = ks * 8 + (lane & 3);
            uint32_t af[4][4];
#pragma unroll
            for (int mi = 0; mi < 4; mi++) {
                int m = warpM * 64 + mi * 16 + (lane >> 2);
                af[mi][0] = As[m * ASTW + base];
                af[mi][1] = As[(m + 8) * ASTW + base];
                af[mi][2] = As[m * ASTW + base + 4];
                af[mi][3] = As[(m + 8) * ASTW + base + 4];
            }
#pragma unroll
            for (int nt = 0; nt < 8; nt++) {
                int n = warpN * 64 + nt * 8 + (lane >> 2);
                uint32_t b0 = Bs[n * BSTW + base];
                uint32_t b1 = Bs[n * BSTW + base + 4];
#pragma unroll
                for (int mi = 0; mi < 4; mi++)
                    mma_f16(acc[mi][nt], af[mi][0], af[mi][1], af[mi][2], af[mi][3], b0, b1);
            }
        }
        __syncthreads();
    }

#pragma unroll
    for (int mi = 0; mi < 4; mi++) {
        int r1 = m0 + warpM * 64 + mi * 16 + (lane >> 2);
        int r2 = r1 + 8;
#pragma unroll
        for (int nt = 0; nt < 8; nt++) {
            int c = n0 + warpN * 64 + nt * 8 + (lane & 3) * 2;
            int h = c >> 7, d = c & 127;
            int b1 = r1 >> 11, t1 = r1 & 2047;
            int b2 = r2 >> 11, t2 = r2 & 2047;
            *(float2*)&C[((long)(b1 * Hx + h) * TT + t1) * HDm + d] =
                make_float2(acc[mi][nt][0], acc[mi][nt][1]);
            *(float2*)&C[((long)(b2 * Hx + h) * TT + t2) * HDm + d] =
                make_float2(acc[mi][nt][2], acc[mi][nt][3]);
        }
    }
}

// Plain fp16 GEMM for output projection (row-major C).
__global__ void __launch_bounds__(128, 2)
tgemm_k(const float* __restrict__ A, const float* __restrict__ Bm,
        float* __restrict__ C, int M, int N, int K)
{
    extern __shared__ uint32_t gsm[];

    const int tid = threadIdx.x;
    const int lane = tid & 31;
    const int wid = tid >> 5;
    const int warpM = wid & 1;
    const int warpN = wid >> 1;
    const int m0 = blockIdx.y * 128;
    const int n0 = blockIdx.x * 128;

    const int arow = tid >> 3;
    const int acolf = (tid & 7) * 4;
    const int acolw = (tid & 7) * 2;

    float acc[4][8][4];
#pragma unroll
    for (int i = 0; i < 4; i++)
#pragma unroll
        for (int jj = 0; jj < 8; jj++)
#pragma unroll
            for (int r = 0; r < 4; r++) acc[i][jj][r] = 0.f;

    uint32_t rah[16], rbh[16];
#pragma unroll
    for (int p = 0; p < 8; p++) {
        float4 v = *(const float4*)&A[(long)(m0 + arow + p * 16) * K + acolf];
        rah[2 * p]     = f2h2(v.x, v.y);
        rah[2 * p + 1] = f2h2(v.z, v.w);
    }
#pragma unroll
    for (int kk = 0; kk < 16; kk++) {
        float f0 = Bm[(long)(2 * kk)     * N + n0 + tid];
        float f1 = Bm[(long)(2 * kk + 1) * N + n0 + tid];
        rbh[kk] = f2h2(f0, f1);
    }

    const int NKT = K / 32;
    for (int kt = 0; kt < NKT; kt++) {
        uint32_t* As = gsm + (kt & 1) * GBUFW;
        uint32_t* Bs = As + A_SZW;

#pragma unroll
        for (int p = 0; p < 8; p++) {
            int m = arow + p * 16;
            *(uint2*)&As[m * ASTW + acolw] = make_uint2(rah[2 * p], rah[2 * p + 1]);
        }
#pragma unroll
        for (int s = 0; s < 4; s++)
            *(uint4*)&Bs[tid * BSTW + s * 4] =
                make_uint4(rbh[4 * s], rbh[4 * s + 1], rbh[4 * s + 2], rbh[4 * s + 3]);
        __syncthreads();

        if (kt + 1 < NKT) {
            int k0 = (kt + 1) * 32;
#pragma unroll
            for (int p = 0; p < 8; p++) {
                float4 v = *(const float4*)&A[(long)(m0 + arow + p * 16) * K + k0 + acolf];
                rah[2 * p]     = f2h2(v.x, v.y);
                rah[2 * p + 1] = f2h2(v.z, v.w);
            }
#pragma unroll
            for (int kk = 0; kk < 16; kk++) {
                float f0 = Bm[(long)(k0 + 2 * kk)     * N + n0 + tid];
                float f1 = Bm[(long)(k0 + 2 * kk + 1) * N + n0 + tid];
                rbh[kk] = f2h2(f0, f1);
            }
        }

#pragma unroll
        for (int ks = 0; ks < 2; ks++) {
            const int base = ks * 8 + (lane & 3);
            uint32_t af[4][4];
#pragma unroll
            for (int mi = 0; mi < 4; mi++) {
                int m = warpM * 64 + mi * 16 + (lane >> 2);
                af[mi][0] = As[m * ASTW + base];
                af[mi][1] = As[(m + 8) * ASTW + base];
                af[mi][2] = As[m * ASTW + base + 4];
                af[mi][3] = As[(m + 8) * ASTW + base + 4];
            }
#pragma unroll
            for (int nt = 0; nt < 8; nt++) {
                int n = warpN * 64 + nt * 8 + (lane >> 2);
                uint32_t b0 = Bs[n * BSTW + base];
                uint32_t b1 = Bs[n * BSTW + base + 4];
#pragma unroll
                for (int mi = 0; mi < 4; mi++)
                    mma_f16(acc[mi][nt], af[mi][0], af[mi][1], af[mi][2], af[mi][3], b0, b1);
            }
        }
        __syncthreads();
    }

#pragma unroll
    for (int mi = 0; mi < 4; mi++) {
        int r1 = m0 + warpM * 64 + mi * 16 + (lane >> 2);
        int r2 = r1 + 8;
#pragma unroll
        for (int nt = 0; nt < 8; nt++) {
            int c = n0 + warpN * 64 + nt * 8 + (lane & 3) * 2;
            *(float2*)&C[(long)r1 * N + c] = make_float2(acc[mi][nt][0], acc[mi][nt][1]);
            *(float2*)&C[(long)r2 * N + c] = make_float2(acc[mi][nt][2], acc[mi][nt][3]);
        }
    }
}

// ---------------------------------------------------------------------------
// RoPE cos/sin table
// ---------------------------------------------------------------------------
__global__ void rope_table_k(float* __restrict__ tab)
{
    int t = blockIdx.x;
    int j = threadIdx.x;
    float inv = exp2f(-(float)j * (13.287712379549449f / 64.0f));
    float ang = (float)t * inv;
    tab[t * 128 + j]      = cosf(ang);
    tab[t * 128 + 64 + j] = sinf(ang);
}

// ---------------------------------------------------------------------------
// Causal flash attention, fp16 operands, fused RoPE: BQ=128, BK=32,
// 256 threads (8 warps). Q frags + S + stats in registers.
// Smem (words): K 2x(32x68) @0; Vt 2x(128x20) @4352; P 128x20 @9472.
// Q staging (128x68) reuses words 0..8703 in phase A.
// ---------------------------------------------------------------------------
#define KSTW 68
#define VSTW 20
#define PSTW 20
#define FK_VOFFW (2 * 32 * KSTW)               // 4352
#define FK_POFFW (FK_VOFFW + 2 * 128 * VSTW)   // 9472
#define FLASH_SMEM_WORDS (FK_POFFW + 128 * PSTW)   // 12032
#define FLASH_SMEM_BYTES (FLASH_SMEM_WORDS * 4)    // 48128
#define SCALE_LOG2E 0.12751744709274227f   // (1/sqrt(128)) * log2(e)

__global__ void __launch_bounds__(256, 1)
flash_k(const float* __restrict__ Q, const float* __restrict__ Kp,
        const float* __restrict__ Vp, const float* __restrict__ tab,
        float* __restrict__ ctx)
{
    extern __shared__ uint32_t smw[];

    const int tid = threadIdx.x;
    const int lane = tid & 31;
    const int w = tid >> 5;
    const int quad = lane >> 2;
    const int j = lane & 3;
    const int qt = gridDim.x - 1 - blockIdx.x;
    const int h  = blockIdx.y;
    const int b  = blockIdx.z;
    const int hk = h >> 2;

    const float* qg = Q  + ((long)(b * NH  + h ) * TT + qt * 128) * HDm;
    const float* kg = Kp + ((long)(b * NKV + hk) * TT) * HDm;
    const float* vg = Vp + ((long)(b * NKV + hk) * TT) * HDm;

    // ---- Phase A: stage Q with fused RoPE + scale, fp16, into smem ----
    for (int i = tid; i < 128 * 16; i += 256) {
        int r = i >> 4;
        int c4 = (i & 15) * 4;
        int t = qt * 128 + r;
        float4 x1 = *(const float4*)&qg[(long)r * HDm + c4];
        float4 x2 = *(const float4*)&qg[(long)r * HDm + c4 + 64];
        float4 cs = *(const float4*)&tab[t * 128 + c4];
        float4 sn = *(const float4*)&tab[t * 128 + 64 + c4];
        float o1x = (x1.x * cs.x - x2.x * sn.x) * SCALE_LOG2E;
        float o1y = (x1.y * cs.y - x2.y * sn.y) * SCALE_LOG2E;
        float o1z = (x1.z * cs.z - x2.z * sn.z) * SCALE_LOG2E;
        float o1w = (x1.w * cs.w - x2.w * sn.w) * SCALE_LOG2E;
        float o2x = (x2.x * cs.x + x1.x * sn.x) * SCALE_LOG2E;
        float o2y = (x2.y * cs.y + x1.y * sn.y) * SCALE_LOG2E;
        float o2z = (x2.z * cs.z + x1.z * sn.z) * SCALE_LOG2E;
        float o2w = (x2.w * cs.w + x1.w * sn.w) * SCALE_LOG2E;
        int wbase = r * KSTW + (c4 >> 1);
        *(uint2*)&smw[wbase]      = make_uint2(f2h2(o1x, o1y), f2h2(o1z, o1w));
        *(uint2*)&smw[wbase + 32] = make_uint2(f2h2(o2x, o2y), f2h2(o2z, o2w));
    }
    __syncthreads();

    uint32_t qf[8][4];
    {
        int r = w * 16 + quad;
#pragma unroll
        for (int ks = 0; ks < 8; ks++) {
            int base = ks * 8 + j;
            qf[ks][0] = smw[r * KSTW + base];
            qf[ks][1] = smw[(r + 8) * KSTW + base];
            qf[ks][2] = smw[r * KSTW + base + 4];
            qf[ks][3] = smw[(r + 8) * KSTW + base + 4];
        }
    }
    __syncthreads();

    uint32_t* Ks = smw;
    uint32_t* Vt = smw + FK_VOFFW;
    uint32_t* Ps = smw + FK_POFFW;

    float oacc[16][4];
#pragma unroll
    for (int nt = 0; nt < 16; nt++)
#pragma unroll
        for (int r = 0; r < 4; r++) oacc[nt][r] = 0.f;

    float m0 = -INFINITY, m1 = -INFINITY, l0 = 0.f, l1 = 0.f;

    const int nkt = 4 * qt + 4;
    const int prow = w * 16 + quad;
    const int qi1 = qt * 128 + prow;
    const int qi2 = qi1 + 8;

    // K staging ids (2 slots): row r, float col group c4
    // V staging ids: column vn (dim), half of keys vkh
    const int vn = tid & 127, vkh = tid >> 7;

    float4 rk1[2], rk2[2];
    uint32_t vh[8];
#pragma unroll
    for (int s = 0; s < 2; s++) {
        int idx = tid + s * 256;
        int r = idx >> 4, c4 = (idx & 15) * 4;
        rk1[s] = *(const float4*)&kg[(long)r * HDm + c4];
        rk2[s] = *(const float4*)&kg[(long)r * HDm + c4 + 64];
    }
#pragma unroll
    for (int p = 0; p < 8; p++) {
        float f0 = vg[(long)(vkh * 16 + 2 * p)     * HDm + vn];
        float f1 = vg[(long)(vkh * 16 + 2 * p + 1) * HDm + vn];
        vh[p] = f2h2(f0, f1);
    }

    for (int kt = 0; kt < nkt; kt++) {
        uint32_t* Kb = Ks + (kt & 1) * 32 * KSTW;
        uint32_t* Vb = Vt + (kt & 1) * 128 * VSTW;

        // store K tile (rope + fp16) and V tile (transposed fp16)
#pragma unroll
        for (int s = 0; s < 2; s++) {
            int idx = tid + s * 256;
            int r = idx >> 4, c4 = (idx & 15) * 4;
            int t = kt * 32 + r;
            float4 cs = *(const float4*)&tab[t * 128 + c4];
            float4 sn = *(const float4*)&tab[t * 128 + 64 + c4];
            float k1x = rk1[s].x * cs.x - rk2[s].x * sn.x;
            float k1y = rk1[s].y * cs.y - rk2[s].y * sn.y;
            float k1z = rk1[s].z * cs.z - rk2[s].z * sn.z;
            float k1w = rk1[s].w * cs.w - rk2[s].w * sn.w;
            float k2x = rk2[s].x * cs.x + rk1[s].x * sn.x;
            float k2y = rk2[s].y * cs.y + rk1[s].y * sn.y;
            float k2z = rk2[s].z * cs.z + rk1[s].z * sn.z;
            float k2w = rk2[s].w * cs.w + rk1[s].w * sn.w;
            int wbase = r * KSTW + (c4 >> 1);
            *(uint2*)&Kb[wbase]      = make_uint2(f2h2(k1x, k1y), f2h2(k1z, k1w));
            *(uint2*)&Kb[wbase + 32] = make_uint2(f2h2(k2x, k2y), f2h2(k2z, k2w));
        }
        *(uint4*)&Vb[vn * VSTW + vkh * 8]     = make_uint4(vh[0], vh[1], vh[2], vh[3]);
        *(uint4*)&Vb[vn * VSTW + vkh * 8 + 4] = make_uint4(vh[4], vh[5], vh[6], vh[7]);
        __syncthreads();

        // prefetch next tile
        if (kt + 1 < nkt) {
            int kbase = (kt + 1) * 32;
#pragma unroll
            for (int s = 0; s < 2; s++) {
                int idx = tid + s * 256;
                int r = idx >> 4, c4 = (idx & 15) * 4;
                long g = ((long)(kbase + r)) * HDm + c4;
                rk1[s] = *(const float4*)&kg[g];
                rk2[s] = *(const float4*)&kg[g + 64];
            }
#pragma unroll
            for (int p = 0; p < 8; p++) {
                float f0 = vg[(long)(kbase + vkh * 16 + 2 * p)     * HDm + vn];
                float f1 = vg[(long)(kbase + vkh * 16 + 2 * p + 1) * HDm + vn];
                vh[p] = f2h2(f0, f1);
            }
        }

        // ---- S = Q @ K^T (fp16 k16) ----
        float sf[4][4];
#pragma unroll
        for (int nt = 0; nt < 4; nt++)
#pragma unroll
            for (int r = 0; r < 4; r++) sf[nt][r] = 0.f;

#pragma unroll
        for (int ks = 0; ks < 8; ks++) {
#pragma unroll
            for (int nt = 0; nt < 4; nt++) {
                int key = nt * 8 + quad;
                uint32_t b0 = Kb[key * KSTW + ks * 8 + j];
                uint32_t b1 = Kb[key * KSTW + ks * 8 + j + 4];
                mma_f16(sf[nt], qf[ks][0], qf[ks][1], qf[ks][2], qf[ks][3], b0, b1);
            }
        }

        // ---- causal mask (diagonal-region tiles only) ----
        if (kt >= 4 * qt) {
#pragma unroll
            for (int nt = 0; nt < 4; nt++) {
                int kj = kt * 32 + nt * 8 + 2 * j;
                if (kj     > qi1) sf[nt][0] = -INFINITY;
                if (kj + 1 > qi1) sf[nt][1] = -INFINITY;
                if (kj     > qi2) sf[nt][2] = -INFINITY;
                if (kj + 1 > qi2) sf[nt][3] = -INFINITY;
            }
        }

        // ---- online softmax (base 2), quad reduction ----
        float mx0 = -INFINITY, mx1 = -INFINITY;
#pragma unroll
        for (int nt = 0; nt < 4; nt++) {
            mx0 = fmaxf(mx0, fmaxf(sf[nt][0], sf[nt][1]));
            mx1 = fmaxf(mx1, fmaxf(sf[nt][2], sf[nt][3]));
        }
        mx0 = fmaxf(mx0, __shfl_xor_sync(0xffffffffu, mx0, 1));
        mx0 = fmaxf(mx0, __shfl_xor_sync(0xffffffffu, mx0, 2));
        mx1 = fmaxf(mx1, __shfl_xor_sync(0xffffffffu, mx1, 1));
        mx1 = fmaxf(mx1, __shfl_xor_sync(0xffffffffu, mx1, 2));

        float mn0 = fmaxf(m0, mx0);
        float mn1 = fmaxf(m1, mx1);
        float a0 = ex2(m0 - mn0);
        float a1 = ex2(m1 - mn1);
        m0 = mn0; m1 = mn1;

        float s0 = 0.f, s1 = 0.f;
#pragma unroll
        for (int nt = 0; nt < 4; nt++) {
            float p0 = rhf(ex2(sf[nt][0] - mn0));
            float p1 = rhf(ex2(sf[nt][1] - mn0));
            float p2 = rhf(ex2(sf[nt][2] - mn1));
            float p3 = rhf(ex2(sf[nt][3] - mn1));
            s0 += p0 + p1;
            s1 += p2 + p3;
            Ps[prow * PSTW + nt * 4 + j]       = f2h2(p0, p1);
            Ps[(prow + 8) * PSTW + nt * 4 + j] = f2h2(p2, p3);
        }
        s0 += __shfl_xor_sync(0xffffffffu, s0, 1);
        s0 += __shfl_xor_sync(0xffffffffu, s0, 2);
        s1 += __shfl_xor_sync(0xffffffffu, s1, 1);
        s1 += __shfl_xor_sync(0xffffffffu, s1, 2);
        l0 = l0 * a0 + s0;
        l1 = l1 * a1 + s1;

#pragma unroll
        for (int nt = 0; nt < 16; nt++) {
            oacc[nt][0] *= a0; oacc[nt][1] *= a0;
            oacc[nt][2] *= a1; oacc[nt][3] *= a1;
        }
        __syncwarp();

        // ---- O += P @ V (fp16 k16, V transposed) ----
#pragma unroll
        for (int kb = 0; kb < 2; kb++) {
            uint32_t pa0 = Ps[prow * PSTW + kb * 8 + j];
            uint32_t pa1 = Ps[(prow + 8) * PSTW + kb * 8 + j];
            uint32_t pa2 = Ps[prow * PSTW + kb * 8 + j + 4];
            uint32_t pa3 = Ps[(prow + 8) * PSTW + kb * 8 + j + 4];
#pragma unroll
            for (int nt = 0; nt < 16; nt++) {
                int n = nt * 8 + quad;
                uint32_t b0 = Vb[n * VSTW + kb * 8 + j];
                uint32_t b1 = Vb[n * VSTW + kb * 8 + j + 4];
                mma_f16(oacc[nt], pa0, pa1, pa2, pa3, b0, b1);
            }
        }
    }

    // ---- normalize + write to (B,T,D) ----
    float li0 = 1.0f / l0;
    float li1 = 1.0f / l1;
    int t1 = qt * 128 + prow;
    int t2 = t1 + 8;
#pragma unroll
    for (int nt = 0; nt < 16; nt++) {
        int n = h * HDm + nt * 8 + 2 * j;
        *(float2*)&ctx[((long)(b * TT + t1)) * DD + n] =
            make_float2(oacc[nt][0] * li0, oacc[nt][1] * li0);
        *(float2*)&ctx[((long)(b * TT + t2)) * DD + n] =
            make_float2(oacc[nt][2] * li1, oacc[nt][3] * li1);
    }
}

// ---------------------------------------------------------------------------
extern "C" void kernel_launch(void* const* d_in, const int* in_sizes, int n_in,
                              void* d_out, int out_size)
{
    const float* x  = (const float*)d_in[0];
    const float* wq = (const float*)d_in[1];
    const float* wk = (const float*)d_in[2];
    const float* wv = (const float*)d_in[3];
    const float* wo = (const float*)d_in[4];
    float* out = (float*)d_out;

    float *q, *k, *v, *ctx, *tab;
    cudaGetSymbolAddress((void**)&q,   g_q);
    cudaGetSymbolAddress((void**)&k,   g_k);
    cudaGetSymbolAddress((void**)&v,   g_v);
    cudaGetSymbolAddress((void**)&ctx, g_ctx);
    cudaGetSymbolAddress((void**)&tab, g_rope);

    cudaFuncSetAttribute(flash_k, cudaFuncAttributeMaxDynamicSharedMemorySize,
                         FLASH_SMEM_BYTES);

    rope_table_k<<<TT, 64>>>(tab);

    // Fused QKV projection (768 CTAs, fp16 operands)
    tqkv_k<<<dim3(24, 32), 128, GEMM_SMEM_BYTES>>>(x, wq, wk, wv, q, k, v);

    // Flash attention (fp16 operands, fused RoPE)
    flash_k<<<dim3(TT / 128, NH, BB), 256, FLASH_SMEM_BYTES>>>(q, k, v, tab, ctx);

    // Output projection
    tgemm_k<<<dim3(16, 32), 128, GEMM_SMEM_BYTES>>>(ctx, wo, out, MROWS, DD, DD);
}

// round 10
// speedup vs baseline: 1.6261x; 1.6261x over previous
#include <cuda_runtime.h>
#include <cuda_fp16.h>
#include <math.h>
#include <stdint.h>

// Problem constants
#define BB   2
#define TT   2048
#define DD   2048
#define NH   16
#define NKV  4
#define HDm  128
#define MROWS (BB*TT)   // 4096
#define GK   2048

// Scratch
__device__ float g_q[BB*NH*TT*HDm];
__device__ float g_k[BB*NKV*TT*HDm];
__device__ float g_v[BB*NKV*TT*HDm];
__device__ float g_ctx[BB*TT*DD];
__device__ float g_rope[TT*128];                 // [t][0..63]=cos, [64..127]=sin
__device__ __half g_xh[(long)MROWS*GK];          // fp16 activations (x, then ctx)
__device__ __half g_wh[5120L*GK];                // fp16 weights^T: [wq|wk|wv|wo] rows

// ---------------------------------------------------------------------------
// helpers
// ---------------------------------------------------------------------------
__device__ __forceinline__ uint32_t f2h2(float a, float b) {
    __half2 h = __floats2half2_rn(a, b);
    return *reinterpret_cast<uint32_t*>(&h);
}
__device__ __forceinline__ float rhf(float x) {
    return __half2float(__float2half_rn(x));
}
__device__ __forceinline__ float ex2(float x) {
    float y; asm("ex2.approx.f32 %0, %1;" : "=f"(y) : "f"(x)); return y;
}
__device__ __forceinline__ void mma_f16(float c[4],
                                        uint32_t a0, uint32_t a1, uint32_t a2, uint32_t a3,
                                        uint32_t b0, uint32_t b1) {
    asm volatile(
        "mma.sync.aligned.m16n8k16.row.col.f32.f16.f16.f32 "
        "{%0,%1,%2,%3}, {%4,%5,%6,%7}, {%8,%9}, {%0,%1,%2,%3};\n"
        : "+f"(c[0]), "+f"(c[1]), "+f"(c[2]), "+f"(c[3])
        : "r"(a0), "r"(a1), "r"(a2), "r"(a3), "r"(b0), "r"(b1));
}

// ---------------------------------------------------------------------------
// Prep kernels
// ---------------------------------------------------------------------------
// Transpose fp32 weight [K=2048][Nw] -> fp16 rows (nbase+n)[K] of g_wh.
__global__ void wtrans_k(const float* __restrict__ w, int Nw, int nbase,
                         __half* __restrict__ wt)
{
    __shared__ float t[32][33];
    int n0 = blockIdx.x * 32, k0 = blockIdx.y * 32;
#pragma unroll
    for (int i = 0; i < 4; i++)
        t[threadIdx.y + i * 8][threadIdx.x] =
            w[(size_t)(k0 + threadIdx.y + i * 8) * Nw + n0 + threadIdx.x];
    __syncthreads();
#pragma unroll
    for (int i = 0; i < 4; i++) {
        int n = n0 + threadIdx.y + i * 8;
        int k = k0 + threadIdx.x;
        wt[(size_t)(nbase + n) * GK + k] = __float2half(t[threadIdx.x][threadIdx.y + i * 8]);
    }
}

// fp32 -> fp16 elementwise (4 floats / thread).
__global__ void tohalf_k(const float* __restrict__ src, __half* __restrict__ dst)
{
    int i = blockIdx.x * blockDim.x + threadIdx.x;
    float4 v = ((const float4*)src)[i];
    ((uint2*)dst)[i] = make_uint2(f2h2(v.x, v.y), f2h2(v.z, v.w));
}

// ---------------------------------------------------------------------------
// fp16 GEMM core: BM=BN=128, BK=32 (16 k-pair words), 128 threads (4 warps 2x2),
// warp tile 64x64, double-buffered. A/B smem [row][kpair] stride 20 words.
// All operands pre-converted fp16 in global, k-major. Pure LDG->STS->LDS->HMMA.
// ---------------------------------------------------------------------------
#define ASTW 20
#define A_SZW (128 * ASTW)           // 2560 words per operand plane
#define GBUFW (2 * A_SZW)            // 5120 words per buffer
#define GEMM_SMEM_BYTES (2 * GBUFW * 4)   // 40960

// Fused QKV: blockIdx.x selects {wq: 0..15, wk: 16..19, wv: 20..23}.
__global__ void __launch_bounds__(128, 2)
tqkv_k(const __half* __restrict__ Ah, const __half* __restrict__ Wh,
       float* __restrict__ qo, float* __restrict__ ko, float* __restrict__ vo)
{
    extern __shared__ uint32_t gsm[];

    const int bx = blockIdx.x;
    float* C;
    int n0, nrow0, Hx;
    if (bx < 16)      { C = qo; n0 = bx * 128;        nrow0 = n0;        Hx = 16; }
    else if (bx < 20) { C = ko; n0 = (bx - 16) * 128; nrow0 = 2048 + n0; Hx = 4;  }
    else              { C = vo; n0 = (bx - 20) * 128; nrow0 = 2560 + n0; Hx = 4;  }

    const int tid = threadIdx.x;
    const int lane = tid & 31;
    const int wid = tid >> 5;
    const int warpM = wid & 1;
    const int warpN = wid >> 1;
    const int m0 = blockIdx.y * 128;

    const int srow = tid >> 2;        // 0..31 (+p*32)
    const int scolw = (tid & 3) * 4;  // smem word col
    const int scolh = (tid & 3) * 8;  // global half col

    float acc[4][8][4];
#pragma unroll
    for (int i = 0; i < 4; i++)
#pragma unroll
        for (int jj = 0; jj < 8; jj++)
#pragma unroll
            for (int r = 0; r < 4; r++) acc[i][jj][r] = 0.f;

    uint4 ra[4], rb[4];
#pragma unroll
    for (int p = 0; p < 4; p++) {
        ra[p] = *(const uint4*)&Ah[(size_t)(m0 + srow + p * 32) * GK + scolh];
        rb[p] = *(const uint4*)&Wh[(size_t)(nrow0 + srow + p * 32) * GK + scolh];
    }

    const int NKT = GK / 32;
    for (int kt = 0; kt < NKT; kt++) {
        uint32_t* As = gsm + (kt & 1) * GBUFW;
        uint32_t* Bs = As + A_SZW;

#pragma unroll
        for (int p = 0; p < 4; p++) {
            *(uint4*)&As[(srow + p * 32) * ASTW + scolw] = ra[p];
            *(uint4*)&Bs[(srow + p * 32) * ASTW + scolw] = rb[p];
        }
        __syncthreads();

        if (kt + 1 < NKT) {
            int k0 = (kt + 1) * 32;
#pragma unroll
            for (int p = 0; p < 4; p++) {
                ra[p] = *(const uint4*)&Ah[(size_t)(m0 + srow + p * 32) * GK + k0 + scolh];
                rb[p] = *(const uint4*)&Wh[(size_t)(nrow0 + srow + p * 32) * GK + k0 + scolh];
            }
        }

#pragma unroll
        for (int ks = 0; ks < 2; ks++) {
            const int base = ks * 8 + (lane & 3);
            uint32_t af[4][4];
#pragma unroll
            for (int mi = 0; mi < 4; mi++) {
                int m = warpM * 64 + mi * 16 + (lane >> 2);
                af[mi][0] = As[m * ASTW + base];
                af[mi][1] = As[(m + 8) * ASTW + base];
                af[mi][2] = As[m * ASTW + base + 4];
                af[mi][3] = As[(m + 8) * ASTW + base + 4];
            }
#pragma unroll
            for (int nt = 0; nt < 8; nt++) {
                int n = warpN * 64 + nt * 8 + (lane >> 2);
                uint32_t b0 = Bs[n * ASTW + base];
                uint32_t b1 = Bs[n * ASTW + base + 4];
#pragma unroll
                for (int mi = 0; mi < 4; mi++)
                    mma_f16(acc[mi][nt], af[mi][0], af[mi][1], af[mi][2], af[mi][3], b0, b1);
            }
        }
        __syncthreads();
    }

#pragma unroll
    for (int mi = 0; mi < 4; mi++) {
        int r1 = m0 + warpM * 64 + mi * 16 + (lane >> 2);
        int r2 = r1 + 8;
#pragma unroll
        for (int nt = 0; nt < 8; nt++) {
            int c = n0 + warpN * 64 + nt * 8 + (lane & 3) * 2;
            int h = c >> 7, d = c & 127;
            int b1 = r1 >> 11, t1 = r1 & 2047;
            int b2 = r2 >> 11, t2 = r2 & 2047;
            *(float2*)&C[((long)(b1 * Hx + h) * TT + t1) * HDm + d] =
                make_float2(acc[mi][nt][0], acc[mi][nt][1]);
            *(float2*)&C[((long)(b2 * Hx + h) * TT + t2) * HDm + d] =
                make_float2(acc[mi][nt][2], acc[mi][nt][3]);
        }
    }
}

// Output projection GEMM (row-major C), same core.
__global__ void __launch_bounds__(128, 2)
tgemm_k(const __half* __restrict__ Ah, const __half* __restrict__ Wh,
        float* __restrict__ C)
{
    extern __shared__ uint32_t gsm[];

    const int tid = threadIdx.x;
    const int lane = tid & 31;
    const int wid = tid >> 5;
    const int warpM = wid & 1;
    const int warpN = wid >> 1;
    const int m0 = blockIdx.y * 128;
    const int n0 = blockIdx.x * 128;
    const int nrow0 = 3072 + n0;

    const int srow = tid >> 2;
    const int scolw = (tid & 3) * 4;
    const int scolh = (tid & 3) * 8;

    float acc[4][8][4];
#pragma unroll
    for (int i = 0; i < 4; i++)
#pragma unroll
        for (int jj = 0; jj < 8; jj++)
#pragma unroll
            for (int r = 0; r < 4; r++) acc[i][jj][r] = 0.f;

    uint4 ra[4], rb[4];
#pragma unroll
    for (int p = 0; p < 4; p++) {
        ra[p] = *(const uint4*)&Ah[(size_t)(m0 + srow + p * 32) * GK + scolh];
        rb[p] = *(const uint4*)&Wh[(size_t)(nrow0 + srow + p * 32) * GK + scolh];
    }

    const int NKT = GK / 32;
    for (int kt = 0; kt < NKT; kt++) {
        uint32_t* As = gsm + (kt & 1) * GBUFW;
        uint32_t* Bs = As + A_SZW;

#pragma unroll
        for (int p = 0; p < 4; p++) {
            *(uint4*)&As[(srow + p * 32) * ASTW + scolw] = ra[p];
            *(uint4*)&Bs[(srow + p * 32) * ASTW + scolw] = rb[p];
        }
        __syncthreads();

        if (kt + 1 < NKT) {
            int k0 = (kt + 1) * 32;
#pragma unroll
            for (int p = 0; p < 4; p++) {
                ra[p] = *(const uint4*)&Ah[(size_t)(m0 + srow + p * 32) * GK + k0 + scolh];
                rb[p] = *(const uint4*)&Wh[(size_t)(nrow0 + srow + p * 32) * GK + k0 + scolh];
            }
        }

#pragma unroll
        for (int ks = 0; ks < 2; ks++) {
            const int base = ks * 8 + (lane & 3);
            uint32_t af[4][4];
#pragma unroll
            for (int mi = 0; mi < 4; mi++) {
                int m = warpM * 64 + mi * 16 + (lane >> 2);
                af[mi][0] = As[m * ASTW + base];
                af[mi][1] = As[(m + 8) * ASTW + base];
                af[mi][2] = As[m * ASTW + base + 4];
                af[mi][3] = As[(m + 8) * ASTW + base + 4];
            }
#pragma unroll
            for (int nt = 0; nt < 8; nt++) {
                int n = warpN * 64 + nt * 8 + (lane >> 2);
                uint32_t b0 = Bs[n * ASTW + base];
                uint32_t b1 = Bs[n * ASTW + base + 4];
#pragma unroll
                for (int mi = 0; mi < 4; mi++)
                    mma_f16(acc[mi][nt], af[mi][0], af[mi][1], af[mi][2], af[mi][3], b0, b1);
            }
        }
        __syncthreads();
    }

#pragma unroll
    for (int mi = 0; mi < 4; mi++) {
        int r1 = m0 + warpM * 64 + mi * 16 + (lane >> 2);
        int r2 = r1 + 8;
#pragma unroll
        for (int nt = 0; nt < 8; nt++) {
            int c = n0 + warpN * 64 + nt * 8 + (lane & 3) * 2;
            *(float2*)&C[(long)r1 * DD + c] = make_float2(acc[mi][nt][0], acc[mi][nt][1]);
            *(float2*)&C[(long)r2 * DD + c] = make_float2(acc[mi][nt][2], acc[mi][nt][3]);
        }
    }
}

// ---------------------------------------------------------------------------
// RoPE cos/sin table
// ---------------------------------------------------------------------------
__global__ void rope_table_k(float* __restrict__ tab)
{
    int t = blockIdx.x;
    int j = threadIdx.x;
    float inv = exp2f(-(float)j * (13.287712379549449f / 64.0f));
    float ang = (float)t * inv;
    tab[t * 128 + j]      = cosf(ang);
    tab[t * 128 + 64 + j] = sinf(ang);
}

// ---------------------------------------------------------------------------
// Causal flash attention (R9 version, verified): fp16 operands, fused RoPE.
// BQ=128, BK=32, 256 threads (8 warps).
// ---------------------------------------------------------------------------
#define KSTW 68
#define VSTW 20
#define PSTW 20
#define FK_VOFFW (2 * 32 * KSTW)               // 4352
#define FK_POFFW (FK_VOFFW + 2 * 128 * VSTW)   // 9472
#define FLASH_SMEM_WORDS (FK_POFFW + 128 * PSTW)   // 12032
#define FLASH_SMEM_BYTES (FLASH_SMEM_WORDS * 4)    // 48128
#define SCALE_LOG2E 0.12751744709274227f

__global__ void __launch_bounds__(256, 1)
flash_k(const float* __restrict__ Q, const float* __restrict__ Kp,
        const float* __restrict__ Vp, const float* __restrict__ tab,
        float* __restrict__ ctx)
{
    extern __shared__ uint32_t smw[];

    const int tid = threadIdx.x;
    const int lane = tid & 31;
    const int w = tid >> 5;
    const int quad = lane >> 2;
    const int j = lane & 3;
    const int qt = gridDim.x - 1 - blockIdx.x;
    const int h  = blockIdx.y;
    const int b  = blockIdx.z;
    const int hk = h >> 2;

    const float* qg = Q  + ((long)(b * NH  + h ) * TT + qt * 128) * HDm;
    const float* kg = Kp + ((long)(b * NKV + hk) * TT) * HDm;
    const float* vg = Vp + ((long)(b * NKV + hk) * TT) * HDm;

    for (int i = tid; i < 128 * 16; i += 256) {
        int r = i >> 4;
        int c4 = (i & 15) * 4;
        int t = qt * 128 + r;
        float4 x1 = *(const float4*)&qg[(long)r * HDm + c4];
        float4 x2 = *(const float4*)&qg[(long)r * HDm + c4 + 64];
        float4 cs = *(const float4*)&tab[t * 128 + c4];
        float4 sn = *(const float4*)&tab[t * 128 + 64 + c4];
        float o1x = (x1.x * cs.x - x2.x * sn.x) * SCALE_LOG2E;
        float o1y = (x1.y * cs.y - x2.y * sn.y) * SCALE_LOG2E;
        float o1z = (x1.z * cs.z - x2.z * sn.z) * SCALE_LOG2E;
        float o1w = (x1.w * cs.w - x2.w * sn.w) * SCALE_LOG2E;
        float o2x = (x2.x * cs.x + x1.x * sn.x) * SCALE_LOG2E;
        float o2y = (x2.y * cs.y + x1.y * sn.y) * SCALE_LOG2E;
        float o2z = (x2.z * cs.z + x1.z * sn.z) * SCALE_LOG2E;
        float o2w = (x2.w * cs.w + x1.w * sn.w) * SCALE_LOG2E;
        int wbase = r * KSTW + (c4 >> 1);
        *(uint2*)&smw[wbase]      = make_uint2(f2h2(o1x, o1y), f2h2(o1z, o1w));
        *(uint2*)&smw[wbase + 32] = make_uint2(f2h2(o2x, o2y), f2h2(o2z, o2w));
    }
    __syncthreads();

    uint32_t qf[8][4];
    {
        int r = w * 16 + quad;
#pragma unroll
        for (int ks = 0; ks < 8; ks++) {
            int base = ks * 8 + j;
            qf[ks][0] = smw[r * KSTW + base];
            qf[ks][1] = smw[(r + 8) * KSTW + base];
            qf[ks][2] = smw[r * KSTW + base + 4];
            qf[ks][3] = smw[(r + 8) * KSTW + base + 4];
        }
    }
    __syncthreads();

    uint32_t* Ks = smw;
    uint32_t* Vt = smw + FK_VOFFW;
    uint32_t* Ps = smw + FK_POFFW;

    float oacc[16][4];
#pragma unroll
    for (int nt = 0; nt < 16; nt++)
#pragma unroll
        for (int r = 0; r < 4; r++) oacc[nt][r] = 0.f;

    float m0 = -INFINITY, m1 = -INFINITY, l0 = 0.f, l1 = 0.f;

    const int nkt = 4 * qt + 4;
    const int prow = w * 16 + quad;
    const int qi1 = qt * 128 + prow;
    const int qi2 = qi1 + 8;

    const int vn = tid & 127, vkh = tid >> 7;

    float4 rk1[2], rk2[2];
    uint32_t vh[8];
#pragma unroll
    for (int s = 0; s < 2; s++) {
        int idx = tid + s * 256;
        int r = idx >> 4, c4 = (idx & 15) * 4;
        rk1[s] = *(const float4*)&kg[(long)r * HDm + c4];
        rk2[s] = *(const float4*)&kg[(long)r * HDm + c4 + 64];
    }
#pragma unroll
    for (int p = 0; p < 8; p++) {
        float f0 = vg[(long)(vkh * 16 + 2 * p)     * HDm + vn];
        float f1 = vg[(long)(vkh * 16 + 2 * p + 1) * HDm + vn];
        vh[p] = f2h2(f0, f1);
    }

    for (int kt = 0; kt < nkt; kt++) {
        uint32_t* Kb = Ks + (kt & 1) * 32 * KSTW;
        uint32_t* Vb = Vt + (kt & 1) * 128 * VSTW;

#pragma unroll
        for (int s = 0; s < 2; s++) {
            int idx = tid + s * 256;
            int r = idx >> 4, c4 = (idx & 15) * 4;
            int t = kt * 32 + r;
            float4 cs = *(const float4*)&tab[t * 128 + c4];
            float4 sn = *(const float4*)&tab[t * 128 + 64 + c4];
            float k1x = rk1[s].x * cs.x - rk2[s].x * sn.x;
            float k1y = rk1[s].y * cs.y - rk2[s].y * sn.y;
            float k1z = rk1[s].z * cs.z - rk2[s].z * sn.z;
            float k1w = rk1[s].w * cs.w - rk2[s].w * sn.w;
            float k2x = rk2[s].x * cs.x + rk1[s].x * sn.x;
            float k2y = rk2[s].y * cs.y + rk1[s].y * sn.y;
            float k2z = rk2[s].z * cs.z + rk1[s].z * sn.z;
            float k2w = rk2[s].w * cs.w + rk1[s].w * sn.w;
            int wbase = r * KSTW + (c4 >> 1);
            *(uint2*)&Kb[wbase]      = make_uint2(f2h2(k1x, k1y), f2h2(k1z, k1w));
            *(uint2*)&Kb[wbase + 32] = make_uint2(f2h2(k2x, k2y), f2h2(k2z, k2w));
        }
        *(uint4*)&Vb[vn * VSTW + vkh * 8]     = make_uint4(vh[0], vh[1], vh[2], vh[3]);
        *(uint4*)&Vb[vn * VSTW + vkh * 8 + 4] = make_uint4(vh[4], vh[5], vh[6], vh[7]);
        __syncthreads();

        if (kt + 1 < nkt) {
            int kbase = (kt + 1) * 32;
#pragma unroll
            for (int s = 0; s < 2; s++) {
                int idx = tid + s * 256;
                int r = idx >> 4, c4 = (idx & 15) * 4;
                long g = ((long)(kbase + r)) * HDm + c4;
                rk1[s] = *(const float4*)&kg[g];
                rk2[s] = *(const float4*)&kg[g + 64];
            }
#pragma unroll
            for (int p = 0; p < 8; p++) {
                float f0 = vg[(long)(kbase + vkh * 16 + 2 * p)     * HDm + vn];
                float f1 = vg[(long)(kbase + vkh * 16 + 2 * p + 1) * HDm + vn];
                vh[p] = f2h2(f0, f1);
            }
        }

        float sf[4][4];
#pragma unroll
        for (int nt = 0; nt < 4; nt++)
#pragma unroll
            for (int r = 0; r < 4; r++) sf[nt][r] = 0.f;

#pragma unroll
        for (int ks = 0; ks < 8; ks++) {
#pragma unroll
            for (int nt = 0; nt < 4; nt++) {
                int key = nt * 8 + quad;
                uint32_t b0 = Kb[key * KSTW + ks * 8 + j];
                uint32_t b1 = Kb[key * KSTW + ks * 8 + j + 4];
                mma_f16(sf[nt], qf[ks][0], qf[ks][1], qf[ks][2], qf[ks][3], b0, b1);
            }
        }

        if (kt >= 4 * qt) {
#pragma unroll
            for (int nt = 0; nt < 4; nt++) {
                int kj = kt * 32 + nt * 8 + 2 * j;
                if (kj     > qi1) sf[nt][0] = -INFINITY;
                if (kj + 1 > qi1) sf[nt][1] = -INFINITY;
                if (kj     > qi2) sf[nt][2] = -INFINITY;
                if (kj + 1 > qi2) sf[nt][3] = -INFINITY;
            }
        }

        float mx0 = -INFINITY, mx1 = -INFINITY;
#pragma unroll
        for (int nt = 0; nt < 4; nt++) {
            mx0 = fmaxf(mx0, fmaxf(sf[nt][0], sf[nt][1]));
            mx1 = fmaxf(mx1, fmaxf(sf[nt][2], sf[nt][3]));
        }
        mx0 = fmaxf(mx0, __shfl_xor_sync(0xffffffffu, mx0, 1));
        mx0 = fmaxf(mx0, __shfl_xor_sync(0xffffffffu, mx0, 2));
        mx1 = fmaxf(mx1, __shfl_xor_sync(0xffffffffu, mx1, 1));
        mx1 = fmaxf(mx1, __shfl_xor_sync(0xffffffffu, mx1, 2));

        float mn0 = fmaxf(m0, mx0);
        float mn1 = fmaxf(m1, mx1);
        float a0 = ex2(m0 - mn0);
        float a1 = ex2(m1 - mn1);
        m0 = mn0; m1 = mn1;

        float s0 = 0.f, s1 = 0.f;
#pragma unroll
        for (int nt = 0; nt < 4; nt++) {
            float p0 = rhf(ex2(sf[nt][0] - mn0));
            float p1 = rhf(ex2(sf[nt][1] - mn0));
            float p2 = rhf(ex2(sf[nt][2] - mn1));
            float p3 = rhf(ex2(sf[nt][3] - mn1));
            s0 += p0 + p1;
            s1 += p2 + p3;
            Ps[prow * PSTW + nt * 4 + j]       = f2h2(p0, p1);
            Ps[(prow + 8) * PSTW + nt * 4 + j] = f2h2(p2, p3);
        }
        s0 += __shfl_xor_sync(0xffffffffu, s0, 1);
        s0 += __shfl_xor_sync(0xffffffffu, s0, 2);
        s1 += __shfl_xor_sync(0xffffffffu, s1, 1);
        s1 += __shfl_xor_sync(0xffffffffu, s1, 2);
        l0 = l0 * a0 + s0;
        l1 = l1 * a1 + s1;

#pragma unroll
        for (int nt = 0; nt < 16; nt++) {
            oacc[nt][0] *= a0; oacc[nt][1] *= a0;
            oacc[nt][2] *= a1; oacc[nt][3] *= a1;
        }
        __syncwarp();

#pragma unroll
        for (int kb = 0; kb < 2; kb++) {
            uint32_t pa0 = Ps[prow * PSTW + kb * 8 + j];
            uint32_t pa1 = Ps[(prow + 8) * PSTW + kb * 8 + j];
            uint32_t pa2 = Ps[prow * PSTW + kb * 8 + j + 4];
            uint32_t pa3 = Ps[(prow + 8) * PSTW + kb * 8 + j + 4];
#pragma unroll
            for (int nt = 0; nt < 16; nt++) {
                int n = nt * 8 + quad;
                uint32_t b0 = Vb[n * VSTW + kb * 8 + j];
                uint32_t b1 = Vb[n * VSTW + kb * 8 + j + 4];
                mma_f16(oacc[nt], pa0, pa1, pa2, pa3, b0, b1);
            }
        }
    }

    float li0 = 1.0f / l0;
    float li1 = 1.0f / l1;
    int t1 = qt * 128 + prow;
    int t2 = t1 + 8;
#pragma unroll
    for (int nt = 0; nt < 16; nt++) {
        int n = h * HDm + nt * 8 + 2 * j;
        *(float2*)&ctx[((long)(b * TT + t1)) * DD + n] =
            make_float2(oacc[nt][0] * li0, oacc[nt][1] * li0);
        *(float2*)&ctx[((long)(b * TT + t2)) * DD + n] =
            make_float2(oacc[nt][2] * li1, oacc[nt][3] * li1);
    }
}

// ---------------------------------------------------------------------------
extern "C" void kernel_launch(void* const* d_in, const int* in_sizes, int n_in,
                              void* d_out, int out_size)
{
    const float* x  = (const float*)d_in[0];
    const float* wq = (const float*)d_in[1];
    const float* wk = (const float*)d_in[2];
    const float* wv = (const float*)d_in[3];
    const float* wo = (const float*)d_in[4];
    float* out = (float*)d_out;

    float *q, *k, *v, *ctx, *tab;
    __half *xh, *wh;
    cudaGetSymbolAddress((void**)&q,   g_q);
    cudaGetSymbolAddress((void**)&k,   g_k);
    cudaGetSymbolAddress((void**)&v,   g_v);
    cudaGetSymbolAddress((void**)&ctx, g_ctx);
    cudaGetSymbolAddress((void**)&tab, g_rope);
    cudaGetSymbolAddress((void**)&xh,  g_xh);
    cudaGetSymbolAddress((void**)&wh,  g_wh);

    cudaFuncSetAttribute(flash_k, cudaFuncAttributeMaxDynamicSharedMemorySize,
                         FLASH_SMEM_BYTES);

    rope_table_k<<<TT, 64>>>(tab);

    // Prep: transpose+fp16 weights, fp16 x
    dim3 tb(32, 8);
    wtrans_k<<<dim3(64, 64), tb>>>(wq, 2048, 0,    wh);
    wtrans_k<<<dim3(16, 64), tb>>>(wk, 512,  2048, wh);
    wtrans_k<<<dim3(16, 64), tb>>>(wv, 512,  2560, wh);
    wtrans_k<<<dim3(64, 64), tb>>>(wo, 2048, 3072, wh);
    tohalf_k<<<(MROWS * GK / 4) / 256, 256>>>(x, xh);

    // Fused QKV projection (768 CTAs, fp16)
    tqkv_k<<<dim3(24, 32), 128, GEMM_SMEM_BYTES>>>(xh, wh, q, k, v);

    // Flash attention (fp16 operands, fused RoPE)
    flash_k<<<dim3(TT / 128, NH, BB), 256, FLASH_SMEM_BYTES>>>(q, k, v, tab, ctx);

    // ctx -> fp16, then output projection
    tohalf_k<<<(MROWS * GK / 4) / 256, 256>>>(ctx, xh);
    tgemm_k<<<dim3(16, 32), 128, GEMM_SMEM_BYTES>>>(xh, wh, out);
}

// round 11
// speedup vs baseline: 1.7534x; 1.0783x over previous
#include <cuda_runtime.h>
#include <cuda_fp16.h>
#include <math.h>
#include <stdint.h>

// Problem constants
#define BB   2
#define TT   2048
#define DD   2048
#define NH   16
#define NKV  4
#define HDm  128
#define MROWS (BB*TT)   // 4096
#define GK   2048
#define QROWS (BB*NH*TT)
#define KROWS (BB*NKV*TT)

// Scratch
__device__ float g_q[BB*NH*TT*HDm];
__device__ float g_k[BB*NKV*TT*HDm];
__device__ float g_v[BB*NKV*TT*HDm];
__device__ float g_ctx[BB*TT*DD];
__device__ float g_rope[TT*128];                 // [t][0..63]=cos, [64..127]=sin
__device__ __half g_xh[(long)MROWS*GK];          // fp16 activations (x, then ctx)
__device__ __half g_wh[5120L*GK];                // fp16 weights^T
__device__ __half g_qh[(long)QROWS*HDm];         // roped+scaled q, fp16
__device__ __half g_kh[(long)KROWS*HDm];         // roped k, fp16
__device__ __half g_vt[(long)KROWS*HDm];         // v transposed [bhk][d][t], fp16

// ---------------------------------------------------------------------------
// helpers
// ---------------------------------------------------------------------------
__device__ __forceinline__ uint32_t f2h2(float a, float b) {
    __half2 h = __floats2half2_rn(a, b);
    return *reinterpret_cast<uint32_t*>(&h);
}
__device__ __forceinline__ float rhf(float x) {
    return __half2float(__float2half_rn(x));
}
__device__ __forceinline__ float ex2(float x) {
    float y; asm("ex2.approx.f32 %0, %1;" : "=f"(y) : "f"(x)); return y;
}
__device__ __forceinline__ void mma_f16(float c[4],
                                        uint32_t a0, uint32_t a1, uint32_t a2, uint32_t a3,
                                        uint32_t b0, uint32_t b1) {
    asm volatile(
        "mma.sync.aligned.m16n8k16.row.col.f32.f16.f16.f32 "
        "{%0,%1,%2,%3}, {%4,%5,%6,%7}, {%8,%9}, {%0,%1,%2,%3};\n"
        : "+f"(c[0]), "+f"(c[1]), "+f"(c[2]), "+f"(c[3])
        : "r"(a0), "r"(a1), "r"(a2), "r"(a3), "r"(b0), "r"(b1));
}

// ---------------------------------------------------------------------------
// Prep kernels
// ---------------------------------------------------------------------------
__global__ void wtrans_k(const float* __restrict__ w, int Nw, int nbase,
                         __half* __restrict__ wt)
{
    __shared__ float t[32][33];
    int n0 = blockIdx.x * 32, k0 = blockIdx.y * 32;
#pragma unroll
    for (int i = 0; i < 4; i++)
        t[threadIdx.y + i * 8][threadIdx.x] =
            w[(size_t)(k0 + threadIdx.y + i * 8) * Nw + n0 + threadIdx.x];
    __syncthreads();
#pragma unroll
    for (int i = 0; i < 4; i++) {
        int n = n0 + threadIdx.y + i * 8;
        int k = k0 + threadIdx.x;
        wt[(size_t)(nbase + n) * GK + k] = __float2half(t[threadIdx.x][threadIdx.y + i * 8]);
    }
}

__global__ void tohalf_k(const float* __restrict__ src, __half* __restrict__ dst)
{
    int i = blockIdx.x * blockDim.x + threadIdx.x;
    float4 v = ((const float4*)src)[i];
    ((uint2*)dst)[i] = make_uint2(f2h2(v.x, v.y), f2h2(v.z, v.w));
}

__global__ void rope_table_k(float* __restrict__ tab)
{
    int t = blockIdx.x;
    int j = threadIdx.x;
    float inv = exp2f(-(float)j * (13.287712379549449f / 64.0f));
    float ang = (float)t * inv;
    tab[t * 128 + j]      = cosf(ang);
    tab[t * 128 + 64 + j] = sinf(ang);
}

// Rope q (with scale*log2e) and k (no scale) fp32 -> fp16.
#define SCALE_LOG2E 0.12751744709274227f
__global__ void ropeh2_k(const float* __restrict__ qp, const float* __restrict__ kp,
                         const float* __restrict__ tab,
                         __half* __restrict__ qh, __half* __restrict__ kh)
{
    int row = blockIdx.x * 4 + (threadIdx.x >> 6);
    int j = threadIdx.x & 63;
    const float* src;
    __half* dst;
    float sc;
    int r;
    if (row < QROWS) { src = qp; dst = qh; r = row;         sc = SCALE_LOG2E; }
    else             { src = kp; dst = kh; r = row - QROWS; sc = 1.0f; }
    int t = r & 2047;
    float c = tab[t * 128 + j];
    float s = tab[t * 128 + 64 + j];
    const float* p = src + (long)r * 128;
    float x1 = p[j], x2 = p[j + 64];
    dst[(long)r * 128 + j]      = __float2half((x1 * c - x2 * s) * sc);
    dst[(long)r * 128 + j + 64] = __float2half((x2 * c + x1 * s) * sc);
}

// Transpose v fp32 [bhk][t][d] -> fp16 [bhk][d][t].
__global__ void vtrans_k(const float* __restrict__ v, __half* __restrict__ vt)
{
    __shared__ float t[32][33];
    int t0 = blockIdx.x * 32, d0 = blockIdx.y * 32, bhk = blockIdx.z;
    const float* src = v + (size_t)bhk * TT * HDm;
    __half* dst = vt + (size_t)bhk * HDm * TT;
#pragma unroll
    for (int i = 0; i < 4; i++)
        t[threadIdx.y + i * 8][threadIdx.x] =
            src[(size_t)(t0 + threadIdx.y + i * 8) * HDm + d0 + threadIdx.x];
    __syncthreads();
#pragma unroll
    for (int i = 0; i < 4; i++) {
        int d = d0 + threadIdx.y + i * 8;
        dst[(size_t)d * TT + t0 + threadIdx.x] =
            __float2half(t[threadIdx.x][threadIdx.y + i * 8]);
    }
}

// ---------------------------------------------------------------------------
// fp16 GEMM core (R10, unchanged): BM=BN=128, BK=32, 128 threads, 2 CTA/SM.
// ---------------------------------------------------------------------------
#define ASTW 20
#define A_SZW (128 * ASTW)
#define GBUFW (2 * A_SZW)
#define GEMM_SMEM_BYTES (2 * GBUFW * 4)

__global__ void __launch_bounds__(128, 2)
tqkv_k(const __half* __restrict__ Ah, const __half* __restrict__ Wh,
       float* __restrict__ qo, float* __restrict__ ko, float* __restrict__ vo)
{
    extern __shared__ uint32_t gsm[];

    const int bx = blockIdx.x;
    float* C;
    int n0, nrow0, Hx;
    if (bx < 16)      { C = qo; n0 = bx * 128;        nrow0 = n0;        Hx = 16; }
    else if (bx < 20) { C = ko; n0 = (bx - 16) * 128; nrow0 = 2048 + n0; Hx = 4;  }
    else              { C = vo; n0 = (bx - 20) * 128; nrow0 = 2560 + n0; Hx = 4;  }

    const int tid = threadIdx.x;
    const int lane = tid & 31;
    const int wid = tid >> 5;
    const int warpM = wid & 1;
    const int warpN = wid >> 1;
    const int m0 = blockIdx.y * 128;

    const int srow = tid >> 2;
    const int scolw = (tid & 3) * 4;
    const int scolh = (tid & 3) * 8;

    float acc[4][8][4];
#pragma unroll
    for (int i = 0; i < 4; i++)
#pragma unroll
        for (int jj = 0; jj < 8; jj++)
#pragma unroll
            for (int r = 0; r < 4; r++) acc[i][jj][r] = 0.f;

    uint4 ra[4], rb[4];
#pragma unroll
    for (int p = 0; p < 4; p++) {
        ra[p] = *(const uint4*)&Ah[(size_t)(m0 + srow + p * 32) * GK + scolh];
        rb[p] = *(const uint4*)&Wh[(size_t)(nrow0 + srow + p * 32) * GK + scolh];
    }

    const int NKT = GK / 32;
    for (int kt = 0; kt < NKT; kt++) {
        uint32_t* As = gsm + (kt & 1) * GBUFW;
        uint32_t* Bs = As + A_SZW;

#pragma unroll
        for (int p = 0; p < 4; p++) {
            *(uint4*)&As[(srow + p * 32) * ASTW + scolw] = ra[p];
            *(uint4*)&Bs[(srow + p * 32) * ASTW + scolw] = rb[p];
        }
        __syncthreads();

        if (kt + 1 < NKT) {
            int k0 = (kt + 1) * 32;
#pragma unroll
            for (int p = 0; p < 4; p++) {
                ra[p] = *(const uint4*)&Ah[(size_t)(m0 + srow + p * 32) * GK + k0 + scolh];
                rb[p] = *(const uint4*)&Wh[(size_t)(nrow0 + srow + p * 32) * GK + k0 + scolh];
            }
        }

#pragma unroll
        for (int ks = 0; ks < 2; ks++) {
            const int base = ks * 8 + (lane & 3);
            uint32_t af[4][4];
#pragma unroll
            for (int mi = 0; mi < 4; mi++) {
                int m = warpM * 64 + mi * 16 + (lane >> 2);
                af[mi][0] = As[m * ASTW + base];
                af[mi][1] = As[(m + 8) * ASTW + base];
                af[mi][2] = As[m * ASTW + base + 4];
                af[mi][3] = As[(m + 8) * ASTW + base + 4];
            }
#pragma unroll
            for (int nt = 0; nt < 8; nt++) {
                int n = warpN * 64 + nt * 8 + (lane >> 2);
                uint32_t b0 = Bs[n * ASTW + base];
                uint32_t b1 = Bs[n * ASTW + base + 4];
#pragma unroll
                for (int mi = 0; mi < 4; mi++)
                    mma_f16(acc[mi][nt], af[mi][0], af[mi][1], af[mi][2], af[mi][3], b0, b1);
            }
        }
        __syncthreads();
    }

#pragma unroll
    for (int mi = 0; mi < 4; mi++) {
        int r1 = m0 + warpM * 64 + mi * 16 + (lane >> 2);
        int r2 = r1 + 8;
#pragma unroll
        for (int nt = 0; nt < 8; nt++) {
            int c = n0 + warpN * 64 + nt * 8 + (lane & 3) * 2;
            int h = c >> 7, d = c & 127;
            int b1 = r1 >> 11, t1 = r1 & 2047;
            int b2 = r2 >> 11, t2 = r2 & 2047;
            *(float2*)&C[((long)(b1 * Hx + h) * TT + t1) * HDm + d] =
                make_float2(acc[mi][nt][0], acc[mi][nt][1]);
            *(float2*)&C[((long)(b2 * Hx + h) * TT + t2) * HDm + d] =
                make_float2(acc[mi][nt][2], acc[mi][nt][3]);
        }
    }
}

__global__ void __launch_bounds__(128, 2)
tgemm_k(const __half* __restrict__ Ah, const __half* __restrict__ Wh,
        float* __restrict__ C)
{
    extern __shared__ uint32_t gsm[];

    const int tid = threadIdx.x;
    const int lane = tid & 31;
    const int wid = tid >> 5;
    const int warpM = wid & 1;
    const int warpN = wid >> 1;
    const int m0 = blockIdx.y * 128;
    const int n0 = blockIdx.x * 128;
    const int nrow0 = 3072 + n0;

    const int srow = tid >> 2;
    const int scolw = (tid & 3) * 4;
    const int scolh = (tid & 3) * 8;

    float acc[4][8][4];
#pragma unroll
    for (int i = 0; i < 4; i++)
#pragma unroll
        for (int jj = 0; jj < 8; jj++)
#pragma unroll
            for (int r = 0; r < 4; r++) acc[i][jj][r] = 0.f;

    uint4 ra[4], rb[4];
#pragma unroll
    for (int p = 0; p < 4; p++) {
        ra[p] = *(const uint4*)&Ah[(size_t)(m0 + srow + p * 32) * GK + scolh];
        rb[p] = *(const uint4*)&Wh[(size_t)(nrow0 + srow + p * 32) * GK + scolh];
    }

    const int NKT = GK / 32;
    for (int kt = 0; kt < NKT; kt++) {
        uint32_t* As = gsm + (kt & 1) * GBUFW;
        uint32_t* Bs = As + A_SZW;

#pragma unroll
        for (int p = 0; p < 4; p++) {
            *(uint4*)&As[(srow + p * 32) * ASTW + scolw] = ra[p];
            *(uint4*)&Bs[(srow + p * 32) * ASTW + scolw] = rb[p];
        }
        __syncthreads();

        if (kt + 1 < NKT) {
            int k0 = (kt + 1) * 32;
#pragma unroll
            for (int p = 0; p < 4; p++) {
                ra[p] = *(const uint4*)&Ah[(size_t)(m0 + srow + p * 32) * GK + k0 + scolh];
                rb[p] = *(const uint4*)&Wh[(size_t)(nrow0 + srow + p * 32) * GK + k0 + scolh];
            }
        }

#pragma unroll
        for (int ks = 0; ks < 2; ks++) {
            const int base = ks * 8 + (lane & 3);
            uint32_t af[4][4];
#pragma unroll
            for (int mi = 0; mi < 4; mi++) {
                int m = warpM * 64 + mi * 16 + (lane >> 2);
                af[mi][0] = As[m * ASTW + base];
                af[mi][1] = As[(m + 8) * ASTW + base];
                af[mi][2] = As[m * ASTW + base + 4];
                af[mi][3] = As[(m + 8) * ASTW + base + 4];
            }
#pragma unroll
            for (int nt = 0; nt < 8; nt++) {
                int n = warpN * 64 + nt * 8 + (lane >> 2);
                uint32_t b0 = Bs[n * ASTW + base];
                uint32_t b1 = Bs[n * ASTW + base + 4];
#pragma unroll
                for (int mi = 0; mi < 4; mi++)
                    mma_f16(acc[mi][nt], af[mi][0], af[mi][1], af[mi][2], af[mi][3], b0, b1);
            }
        }
        __syncthreads();
    }

#pragma unroll
    for (int mi = 0; mi < 4; mi++) {
        int r1 = m0 + warpM * 64 + mi * 16 + (lane >> 2);
        int r2 = r1 + 8;
#pragma unroll
        for (int nt = 0; nt < 8; nt++) {
            int c = n0 + warpN * 64 + nt * 8 + (lane & 3) * 2;
            *(float2*)&C[(long)r1 * DD + c] = make_float2(acc[mi][nt][0], acc[mi][nt][1]);
            *(float2*)&C[(long)r2 * DD + c] = make_float2(acc[mi][nt][2], acc[mi][nt][3]);
        }
    }
}

// ---------------------------------------------------------------------------
// Causal flash attention: fp16 pre-roped operands, pure-copy staging.
// BQ=128, BK=32, 256 threads (8 warps). Q frags + S + stats in registers.
// ---------------------------------------------------------------------------
#define KSTW 68
#define VSTW 20
#define PSTW 20
#define FK_VOFFW (2 * 32 * KSTW)               // 4352
#define FK_POFFW (FK_VOFFW + 2 * 128 * VSTW)   // 9472
#define FLASH_SMEM_WORDS (FK_POFFW + 128 * PSTW)   // 12032
#define FLASH_SMEM_BYTES (FLASH_SMEM_WORDS * 4)    // 48128

__global__ void __launch_bounds__(256, 1)
flash_k(const __half* __restrict__ Qh, const __half* __restrict__ Kh,
        const __half* __restrict__ Vt, float* __restrict__ ctx)
{
    extern __shared__ uint32_t smw[];

    const int tid = threadIdx.x;
    const int lane = tid & 31;
    const int w = tid >> 5;
    const int quad = lane >> 2;
    const int j = lane & 3;
    const int qt = gridDim.x - 1 - blockIdx.x;
    const int h  = blockIdx.y;
    const int b  = blockIdx.z;
    const int hk = h >> 2;

    const __half* qg = Qh + ((long)(b * NH  + h ) * TT + qt * 128) * HDm;
    const __half* kg = Kh + ((long)(b * NKV + hk) * TT) * HDm;
    const __half* vg = Vt + ((long)(b * NKV + hk) * HDm) * TT;   // [d][t]

    // ---- Phase A: stage Q (already roped+scaled fp16) -> smem ----
    for (int i = tid; i < 2048; i += 256) {
        int r = i >> 4, c = i & 15;
        *(uint4*)&smw[r * KSTW + c * 4] = *(const uint4*)&qg[(long)r * HDm + c * 8];
    }
    __syncthreads();

    uint32_t qf[8][4];
    {
        int r = w * 16 + quad;
#pragma unroll
        for (int ks = 0; ks < 8; ks++) {
            int base = ks * 8 + j;
            qf[ks][0] = smw[r * KSTW + base];
            qf[ks][1] = smw[(r + 8) * KSTW + base];
            qf[ks][2] = smw[r * KSTW + base + 4];
            qf[ks][3] = smw[(r + 8) * KSTW + base + 4];
        }
    }
    __syncthreads();

    uint32_t* Ks = smw;
    uint32_t* Vtile = smw + FK_VOFFW;
    uint32_t* Ps = smw + FK_POFFW;

    float oacc[16][4];
#pragma unroll
    for (int nt = 0; nt < 16; nt++)
#pragma unroll
        for (int r = 0; r < 4; r++) oacc[nt][r] = 0.f;

    float m0 = -INFINITY, m1 = -INFINITY, l0 = 0.f, l1 = 0.f;

    const int nkt = 4 * qt + 4;
    const int prow = w * 16 + quad;
    const int qi1 = qt * 128 + prow;
    const int qi2 = qi1 + 8;

    const int kr = tid >> 4, kc = tid & 15;        // K staging ids (+16 rows for s=1)
    const int vn = tid & 127, vkh = tid >> 7;      // V staging ids

    uint4 rk[2], rv[2];
#pragma unroll
    for (int s = 0; s < 2; s++) {
        rk[s] = *(const uint4*)&kg[(long)(kr + s * 16) * HDm + kc * 8];
        rv[s] = *(const uint4*)&vg[(long)vn * TT + vkh * 16 + s * 8];
    }

    for (int kt = 0; kt < nkt; kt++) {
        uint32_t* Kb = Ks + (kt & 1) * 32 * KSTW;
        uint32_t* Vb = Vtile + (kt & 1) * 128 * VSTW;

#pragma unroll
        for (int s = 0; s < 2; s++) {
            *(uint4*)&Kb[(kr + s * 16) * KSTW + kc * 4] = rk[s];
            *(uint4*)&Vb[vn * VSTW + vkh * 8 + s * 4]   = rv[s];
        }
        __syncthreads();

        if (kt + 1 < nkt) {
            int kbase = (kt + 1) * 32;
#pragma unroll
            for (int s = 0; s < 2; s++) {
                rk[s] = *(const uint4*)&kg[(long)(kbase + kr + s * 16) * HDm + kc * 8];
                rv[s] = *(const uint4*)&vg[(long)vn * TT + kbase + vkh * 16 + s * 8];
            }
        }

        // ---- S = Q @ K^T (fp16 k16) ----
        float sf[4][4];
#pragma unroll
        for (int nt = 0; nt < 4; nt++)
#pragma unroll
            for (int r = 0; r < 4; r++) sf[nt][r] = 0.f;

#pragma unroll
        for (int ks = 0; ks < 8; ks++) {
#pragma unroll
            for (int nt = 0; nt < 4; nt++) {
                int key = nt * 8 + quad;
                uint32_t b0 = Kb[key * KSTW + ks * 8 + j];
                uint32_t b1 = Kb[key * KSTW + ks * 8 + j + 4];
                mma_f16(sf[nt], qf[ks][0], qf[ks][1], qf[ks][2], qf[ks][3], b0, b1);
            }
        }

        // ---- causal mask (diagonal-region tiles only) ----
        if (kt >= 4 * qt) {
#pragma unroll
            for (int nt = 0; nt < 4; nt++) {
                int kj = kt * 32 + nt * 8 + 2 * j;
                if (kj     > qi1) sf[nt][0] = -INFINITY;
                if (kj + 1 > qi1) sf[nt][1] = -INFINITY;
                if (kj     > qi2) sf[nt][2] = -INFINITY;
                if (kj + 1 > qi2) sf[nt][3] = -INFINITY;
            }
        }

        // ---- online softmax (base 2), quad reduction ----
        float mx0 = -INFINITY, mx1 = -INFINITY;
#pragma unroll
        for (int nt = 0; nt < 4; nt++) {
            mx0 = fmaxf(mx0, fmaxf(sf[nt][0], sf[nt][1]));
            mx1 = fmaxf(mx1, fmaxf(sf[nt][2], sf[nt][3]));
        }
        mx0 = fmaxf(mx0, __shfl_xor_sync(0xffffffffu, mx0, 1));
        mx0 = fmaxf(mx0, __shfl_xor_sync(0xffffffffu, mx0, 2));
        mx1 = fmaxf(mx1, __shfl_xor_sync(0xffffffffu, mx1, 1));
        mx1 = fmaxf(mx1, __shfl_xor_sync(0xffffffffu, mx1, 2));

        float mn0 = fmaxf(m0, mx0);
        float mn1 = fmaxf(m1, mx1);
        float a0 = ex2(m0 - mn0);
        float a1 = ex2(m1 - mn1);
        m0 = mn0; m1 = mn1;

        float s0 = 0.f, s1 = 0.f;
#pragma unroll
        for (int nt = 0; nt < 4; nt++) {
            float p0 = rhf(ex2(sf[nt][0] - mn0));
            float p1 = rhf(ex2(sf[nt][1] - mn0));
            float p2 = rhf(ex2(sf[nt][2] - mn1));
            float p3 = rhf(ex2(sf[nt][3] - mn1));
            s0 += p0 + p1;
            s1 += p2 + p3;
            Ps[prow * PSTW + nt * 4 + j]       = f2h2(p0, p1);
            Ps[(prow + 8) * PSTW + nt * 4 + j] = f2h2(p2, p3);
        }
        s0 += __shfl_xor_sync(0xffffffffu, s0, 1);
        s0 += __shfl_xor_sync(0xffffffffu, s0, 2);
        s1 += __shfl_xor_sync(0xffffffffu, s1, 1);
        s1 += __shfl_xor_sync(0xffffffffu, s1, 2);
        l0 = l0 * a0 + s0;
        l1 = l1 * a1 + s1;

#pragma unroll
        for (int nt = 0; nt < 16; nt++) {
            oacc[nt][0] *= a0; oacc[nt][1] *= a0;
            oacc[nt][2] *= a1; oacc[nt][3] *= a1;
        }
        __syncwarp();

        // ---- O += P @ V (fp16 k16, V transposed) ----
#pragma unroll
        for (int kb = 0; kb < 2; kb++) {
            uint32_t pa0 = Ps[prow * PSTW + kb * 8 + j];
            uint32_t pa1 = Ps[(prow + 8) * PSTW + kb * 8 + j];
            uint32_t pa2 = Ps[prow * PSTW + kb * 8 + j + 4];
            uint32_t pa3 = Ps[(prow + 8) * PSTW + kb * 8 + j + 4];
#pragma unroll
            for (int nt = 0; nt < 16; nt++) {
                int n = nt * 8 + quad;
                uint32_t b0 = Vb[n * VSTW + kb * 8 + j];
                uint32_t b1 = Vb[n * VSTW + kb * 8 + j + 4];
                mma_f16(oacc[nt], pa0, pa1, pa2, pa3, b0, b1);
            }
        }
    }

    // ---- normalize + write to (B,T,D) ----
    float li0 = 1.0f / l0;
    float li1 = 1.0f / l1;
    int t1 = qt * 128 + prow;
    int t2 = t1 + 8;
#pragma unroll
    for (int nt = 0; nt < 16; nt++) {
        int n = h * HDm + nt * 8 + 2 * j;
        *(float2*)&ctx[((long)(b * TT + t1)) * DD + n] =
            make_float2(oacc[nt][0] * li0, oacc[nt][1] * li0);
        *(float2*)&ctx[((long)(b * TT + t2)) * DD + n] =
            make_float2(oacc[nt][2] * li1, oacc[nt][3] * li1);
    }
}

// ---------------------------------------------------------------------------
extern "C" void kernel_launch(void* const* d_in, const int* in_sizes, int n_in,
                              void* d_out, int out_size)
{
    const float* x  = (const float*)d_in[0];
    const float* wq = (const float*)d_in[1];
    const float* wk = (const float*)d_in[2];
    const float* wv = (const float*)d_in[3];
    const float* wo = (const float*)d_in[4];
    float* out = (float*)d_out;

    float *q, *k, *v, *ctx, *tab;
    __half *xh, *wh, *qh, *kh, *vt;
    cudaGetSymbolAddress((void**)&q,   g_q);
    cudaGetSymbolAddress((void**)&k,   g_k);
    cudaGetSymbolAddress((void**)&v,   g_v);
    cudaGetSymbolAddress((void**)&ctx, g_ctx);
    cudaGetSymbolAddress((void**)&tab, g_rope);
    cudaGetSymbolAddress((void**)&xh,  g_xh);
    cudaGetSymbolAddress((void**)&wh,  g_wh);
    cudaGetSymbolAddress((void**)&qh,  g_qh);
    cudaGetSymbolAddress((void**)&kh,  g_kh);
    cudaGetSymbolAddress((void**)&vt,  g_vt);

    cudaFuncSetAttribute(flash_k, cudaFuncAttributeMaxDynamicSharedMemorySize,
                         FLASH_SMEM_BYTES);

    rope_table_k<<<TT, 64>>>(tab);

    // Prep: transpose+fp16 weights, fp16 x
    dim3 tb(32, 8);
    wtrans_k<<<dim3(64, 64), tb>>>(wq, 2048, 0,    wh);
    wtrans_k<<<dim3(16, 64), tb>>>(wk, 512,  2048, wh);
    wtrans_k<<<dim3(16, 64), tb>>>(wv, 512,  2560, wh);
    wtrans_k<<<dim3(64, 64), tb>>>(wo, 2048, 3072, wh);
    tohalf_k<<<(MROWS * GK / 4) / 256, 256>>>(x, xh);

    // Fused QKV projection
    tqkv_k<<<dim3(24, 32), 128, GEMM_SMEM_BYTES>>>(xh, wh, q, k, v);

    // Rope q/k -> fp16; transpose v -> fp16 [d][t]
    ropeh2_k<<<(QROWS + KROWS) / 4, 256>>>(q, k, tab, qh, kh);
    vtrans_k<<<dim3(TT / 32, HDm / 32, BB * NKV), tb>>>(v, vt);

    // Flash attention (pure-copy staging)
    flash_k<<<dim3(TT / 128, NH, BB), 256, FLASH_SMEM_BYTES>>>(qh, kh, vt, ctx);

    // ctx -> fp16, then output projection
    tohalf_k<<<(MROWS * GK / 4) / 256, 256>>>(ctx, xh);
    tgemm_k<<<dim3(16, 32), 128, GEMM_SMEM_BYTES>>>(xh, wh, out);
}

// round 12
// speedup vs baseline: 2.0113x; 1.1471x over previous
#include <cuda_runtime.h>
#include <cuda_fp16.h>
#include <math.h>
#include <stdint.h>

// Problem constants
#define BB   2
#define TT   2048
#define DD   2048
#define NH   16
#define NKV  4
#define HDm  128
#define MROWS (BB*TT)   // 4096
#define GK   2048
#define QROWS (BB*NH*TT)
#define KROWS (BB*NKV*TT)

// Scratch
__device__ float g_q[BB*NH*TT*HDm];
__device__ float g_k[BB*NKV*TT*HDm];
__device__ float g_v[BB*NKV*TT*HDm];
__device__ float g_rope[TT*128];
__device__ __half g_xh[(long)MROWS*GK];          // fp16 activations (x, then attn ctx)
__device__ __half g_wh[5120L*GK];                // fp16 weights^T
__device__ __half g_qh[(long)QROWS*HDm];
__device__ __half g_kh[(long)KROWS*HDm];
__device__ __half g_vt[(long)KROWS*HDm];         // v transposed [bhk][d][t]

// ---------------------------------------------------------------------------
// helpers
// ---------------------------------------------------------------------------
__device__ __forceinline__ uint32_t f2h2(float a, float b) {
    __half2 h = __floats2half2_rn(a, b);
    return *reinterpret_cast<uint32_t*>(&h);
}
__device__ __forceinline__ float rhf(float x) {
    return __half2float(__float2half_rn(x));
}
__device__ __forceinline__ float ex2(float x) {
    float y; asm("ex2.approx.f32 %0, %1;" : "=f"(y) : "f"(x)); return y;
}
__device__ __forceinline__ void mma_f16(float c[4],
                                        uint32_t a0, uint32_t a1, uint32_t a2, uint32_t a3,
                                        uint32_t b0, uint32_t b1) {
    asm volatile(
        "mma.sync.aligned.m16n8k16.row.col.f32.f16.f16.f32 "
        "{%0,%1,%2,%3}, {%4,%5,%6,%7}, {%8,%9}, {%0,%1,%2,%3};\n"
        : "+f"(c[0]), "+f"(c[1]), "+f"(c[2]), "+f"(c[3])
        : "r"(a0), "r"(a1), "r"(a2), "r"(a3), "r"(b0), "r"(b1));
}
__device__ __forceinline__ void cpa16(uint32_t dst, const void* src) {
    asm volatile("cp.async.cg.shared.global [%0], [%1], 16;\n"
                 :: "r"(dst), "l"(src) : "memory");
}
#define CP_COMMIT() asm volatile("cp.async.commit_group;\n" ::: "memory")
#define CP_WAIT(n)  asm volatile("cp.async.wait_group %0;\n" :: "n"(n) : "memory")

// ---------------------------------------------------------------------------
// Prep kernels
// ---------------------------------------------------------------------------
__global__ void wtrans_k(const float* __restrict__ w, int Nw, int nbase,
                         __half* __restrict__ wt)
{
    __shared__ float t[32][33];
    int n0 = blockIdx.x * 32, k0 = blockIdx.y * 32;
#pragma unroll
    for (int i = 0; i < 4; i++)
        t[threadIdx.y + i * 8][threadIdx.x] =
            w[(size_t)(k0 + threadIdx.y + i * 8) * Nw + n0 + threadIdx.x];
    __syncthreads();
#pragma unroll
    for (int i = 0; i < 4; i++) {
        int n = n0 + threadIdx.y + i * 8;
        int k = k0 + threadIdx.x;
        wt[(size_t)(nbase + n) * GK + k] = __float2half(t[threadIdx.x][threadIdx.y + i * 8]);
    }
}

__global__ void tohalf_k(const float* __restrict__ src, __half* __restrict__ dst)
{
    int i = blockIdx.x * blockDim.x + threadIdx.x;
    float4 v = ((const float4*)src)[i];
    ((uint2*)dst)[i] = make_uint2(f2h2(v.x, v.y), f2h2(v.z, v.w));
}

__global__ void rope_table_k(float* __restrict__ tab)
{
    int t = blockIdx.x;
    int j = threadIdx.x;
    float inv = exp2f(-(float)j * (13.287712379549449f / 64.0f));
    float ang = (float)t * inv;
    tab[t * 128 + j]      = cosf(ang);
    tab[t * 128 + 64 + j] = sinf(ang);
}

#define SCALE_LOG2E 0.12751744709274227f
__global__ void ropeh2_k(const float* __restrict__ qp, const float* __restrict__ kp,
                         const float* __restrict__ tab,
                         __half* __restrict__ qh, __half* __restrict__ kh)
{
    int row = blockIdx.x * 4 + (threadIdx.x >> 6);
    int j = threadIdx.x & 63;
    const float* src;
    __half* dst;
    float sc;
    int r;
    if (row < QROWS) { src = qp; dst = qh; r = row;         sc = SCALE_LOG2E; }
    else             { src = kp; dst = kh; r = row - QROWS; sc = 1.0f; }
    int t = r & 2047;
    float c = tab[t * 128 + j];
    float s = tab[t * 128 + 64 + j];
    const float* p = src + (long)r * 128;
    float x1 = p[j], x2 = p[j + 64];
    dst[(long)r * 128 + j]      = __float2half((x1 * c - x2 * s) * sc);
    dst[(long)r * 128 + j + 64] = __float2half((x2 * c + x1 * s) * sc);
}

__global__ void vtrans_k(const float* __restrict__ v, __half* __restrict__ vt)
{
    __shared__ float t[32][33];
    int t0 = blockIdx.x * 32, d0 = blockIdx.y * 32, bhk = blockIdx.z;
    const float* src = v + (size_t)bhk * TT * HDm;
    __half* dst = vt + (size_t)bhk * HDm * TT;
#pragma unroll
    for (int i = 0; i < 4; i++)
        t[threadIdx.y + i * 8][threadIdx.x] =
            src[(size_t)(t0 + threadIdx.y + i * 8) * HDm + d0 + threadIdx.x];
    __syncthreads();
#pragma unroll
    for (int i = 0; i < 4; i++) {
        int d = d0 + threadIdx.y + i * 8;
        dst[(size_t)d * TT + t0 + threadIdx.x] =
            __float2half(t[threadIdx.x][threadIdx.y + i * 8]);
    }
}

// ---------------------------------------------------------------------------
// fp16 GEMM, 3-stage cp.async pipeline: BM=BN=128, BK=32, 128 threads (4 warps).
// ---------------------------------------------------------------------------
#define ASTW 20
#define A_SZW (128 * ASTW)
#define GBUFW (2 * A_SZW)                  // 5120 words / stage
#define GEMM_STAGE_BYTES (GBUFW * 4)       // 20480
#define GEMM_SMEM_BYTES (3 * GEMM_STAGE_BYTES)   // 61440

#define GEMM_ISSUE(kt, s) do { \
    uint32_t As_ = smb + (s) * GEMM_STAGE_BYTES; \
    uint32_t Bs_ = As_ + A_SZW * 4; \
    int k0_ = (kt) * 32; \
    _Pragma("unroll") \
    for (int p = 0; p < 4; p++) { \
        cpa16(As_ + (uint32_t)(((srow + p * 32) * ASTW + scolw) * 4), \
              &Ah[(size_t)(m0 + srow + p * 32) * GK + k0_ + scolh]); \
        cpa16(Bs_ + (uint32_t)(((srow + p * 32) * ASTW + scolw) * 4), \
              &Wh[(size_t)(nrow0 + srow + p * 32) * GK + k0_ + scolh]); \
    } \
    CP_COMMIT(); \
} while (0)

__global__ void __launch_bounds__(128, 2)
tqkv_k(const __half* __restrict__ Ah, const __half* __restrict__ Wh,
       float* __restrict__ qo, float* __restrict__ ko, float* __restrict__ vo)
{
    extern __shared__ uint32_t gsm[];
    uint32_t smb = (uint32_t)__cvta_generic_to_shared(gsm);

    const int bx = blockIdx.x;
    float* C;
    int n0, nrow0, Hx;
    if (bx < 16)      { C = qo; n0 = bx * 128;        nrow0 = n0;        Hx = 16; }
    else if (bx < 20) { C = ko; n0 = (bx - 16) * 128; nrow0 = 2048 + n0; Hx = 4;  }
    else              { C = vo; n0 = (bx - 20) * 128; nrow0 = 2560 + n0; Hx = 4;  }

    const int tid = threadIdx.x;
    const int lane = tid & 31;
    const int wid = tid >> 5;
    const int warpM = wid & 1;
    const int warpN = wid >> 1;
    const int m0 = blockIdx.y * 128;

    const int srow = tid >> 2;
    const int scolw = (tid & 3) * 4;
    const int scolh = (tid & 3) * 8;

    float acc[4][8][4];
#pragma unroll
    for (int i = 0; i < 4; i++)
#pragma unroll
        for (int jj = 0; jj < 8; jj++)
#pragma unroll
            for (int r = 0; r < 4; r++) acc[i][jj][r] = 0.f;

    const int NKT = GK / 32;
    GEMM_ISSUE(0, 0);
    GEMM_ISSUE(1, 1);

    for (int kt = 0; kt < NKT; kt++) {
        if (kt + 1 < NKT) { CP_WAIT(1); } else { CP_WAIT(0); }
        __syncthreads();
        uint32_t* As = gsm + (kt % 3) * GBUFW;
        uint32_t* Bs = As + A_SZW;

#pragma unroll
        for (int ks = 0; ks < 2; ks++) {
            const int base = ks * 8 + (lane & 3);
            uint32_t af[4][4];
#pragma unroll
            for (int mi = 0; mi < 4; mi++) {
                int m = warpM * 64 + mi * 16 + (lane >> 2);
                af[mi][0] = As[m * ASTW + base];
                af[mi][1] = As[(m + 8) * ASTW + base];
                af[mi][2] = As[m * ASTW + base + 4];
                af[mi][3] = As[(m + 8) * ASTW + base + 4];
            }
#pragma unroll
            for (int nt = 0; nt < 8; nt++) {
                int n = warpN * 64 + nt * 8 + (lane >> 2);
                uint32_t b0 = Bs[n * ASTW + base];
                uint32_t b1 = Bs[n * ASTW + base + 4];
#pragma unroll
                for (int mi = 0; mi < 4; mi++)
                    mma_f16(acc[mi][nt], af[mi][0], af[mi][1], af[mi][2], af[mi][3], b0, b1);
            }
        }
        if (kt + 2 < NKT) GEMM_ISSUE(kt + 2, (kt + 2) % 3);
    }

#pragma unroll
    for (int mi = 0; mi < 4; mi++) {
        int r1 = m0 + warpM * 64 + mi * 16 + (lane >> 2);
        int r2 = r1 + 8;
#pragma unroll
        for (int nt = 0; nt < 8; nt++) {
            int c = n0 + warpN * 64 + nt * 8 + (lane & 3) * 2;
            int h = c >> 7, d = c & 127;
            int b1 = r1 >> 11, t1 = r1 & 2047;
            int b2 = r2 >> 11, t2 = r2 & 2047;
            *(float2*)&C[((long)(b1 * Hx + h) * TT + t1) * HDm + d] =
                make_float2(acc[mi][nt][0], acc[mi][nt][1]);
            *(float2*)&C[((long)(b2 * Hx + h) * TT + t2) * HDm + d] =
                make_float2(acc[mi][nt][2], acc[mi][nt][3]);
        }
    }
}

// Output projection: reads fp16 attn ctx (g_xh), writes fp32 out.
__global__ void __launch_bounds__(128, 2)
tgemm_k(const __half* __restrict__ Ah, const __half* __restrict__ Wh,
        float* __restrict__ C)
{
    extern __shared__ uint32_t gsm[];
    uint32_t smb = (uint32_t)__cvta_generic_to_shared(gsm);

    const int tid = threadIdx.x;
    const int lane = tid & 31;
    const int wid = tid >> 5;
    const int warpM = wid & 1;
    const int warpN = wid >> 1;
    const int m0 = blockIdx.y * 128;
    const int n0 = blockIdx.x * 128;
    const int nrow0 = 3072 + n0;

    const int srow = tid >> 2;
    const int scolw = (tid & 3) * 4;
    const int scolh = (tid & 3) * 8;

    float acc[4][8][4];
#pragma unroll
    for (int i = 0; i < 4; i++)
#pragma unroll
        for (int jj = 0; jj < 8; jj++)
#pragma unroll
            for (int r = 0; r < 4; r++) acc[i][jj][r] = 0.f;

    const int NKT = GK / 32;
    GEMM_ISSUE(0, 0);
    GEMM_ISSUE(1, 1);

    for (int kt = 0; kt < NKT; kt++) {
        if (kt + 1 < NKT) { CP_WAIT(1); } else { CP_WAIT(0); }
        __syncthreads();
        uint32_t* As = gsm + (kt % 3) * GBUFW;
        uint32_t* Bs = As + A_SZW;

#pragma unroll
        for (int ks = 0; ks < 2; ks++) {
            const int base = ks * 8 + (lane & 3);
            uint32_t af[4][4];
#pragma unroll
            for (int mi = 0; mi < 4; mi++) {
                int m = warpM * 64 + mi * 16 + (lane >> 2);
                af[mi][0] = As[m * ASTW + base];
                af[mi][1] = As[(m + 8) * ASTW + base];
                af[mi][2] = As[m * ASTW + base + 4];
                af[mi][3] = As[(m + 8) * ASTW + base + 4];
            }
#pragma unroll
            for (int nt = 0; nt < 8; nt++) {
                int n = warpN * 64 + nt * 8 + (lane >> 2);
                uint32_t b0 = Bs[n * ASTW + base];
                uint32_t b1 = Bs[n * ASTW + base + 4];
#pragma unroll
                for (int mi = 0; mi < 4; mi++)
                    mma_f16(acc[mi][nt], af[mi][0], af[mi][1], af[mi][2], af[mi][3], b0, b1);
            }
        }
        if (kt + 2 < NKT) GEMM_ISSUE(kt + 2, (kt + 2) % 3);
    }

#pragma unroll
    for (int mi = 0; mi < 4; mi++) {
        int r1 = m0 + warpM * 64 + mi * 16 + (lane >> 2);
        int r2 = r1 + 8;
#pragma unroll
        for (int nt = 0; nt < 8; nt++) {
            int c = n0 + warpN * 64 + nt * 8 + (lane & 3) * 2;
            *(float2*)&C[(long)r1 * DD + c] = make_float2(acc[mi][nt][0], acc[mi][nt][1]);
            *(float2*)&C[(long)r2 * DD + c] = make_float2(acc[mi][nt][2], acc[mi][nt][3]);
        }
    }
}

// ---------------------------------------------------------------------------
// Causal flash attention: fp16 pre-roped operands, cp.async double-buffered
// staging, fp16 ctx output. BQ=128, BK=32, 256 threads (8 warps).
// ---------------------------------------------------------------------------
#define KSTW 68
#define VSTW 20
#define PSTW 20
#define FK_VOFFW (2 * 32 * KSTW)               // 4352
#define FK_POFFW (FK_VOFFW + 2 * 128 * VSTW)   // 9472
#define FLASH_SMEM_WORDS (FK_POFFW + 128 * PSTW)   // 12032
#define FLASH_SMEM_BYTES (FLASH_SMEM_WORDS * 4)    // 48128

#define FLASH_ISSUE(kt) do { \
    uint32_t Kb_ = smb + (uint32_t)(((kt) & 1) * 32 * KSTW * 4); \
    uint32_t Vb_ = smb + (uint32_t)(FK_VOFFW * 4 + ((kt) & 1) * 128 * VSTW * 4); \
    int kb0_ = (kt) * 32; \
    cpa16(Kb_ + (uint32_t)((kr * KSTW + kc * 4) * 4), \
          &kg[(long)(kb0_ + kr) * HDm + kc * 8]); \
    cpa16(Kb_ + (uint32_t)(((kr + 16) * KSTW + kc * 4) * 4), \
          &kg[(long)(kb0_ + kr + 16) * HDm + kc * 8]); \
    cpa16(Vb_ + (uint32_t)((vn * VSTW + vkh * 8) * 4), \
          &vg[(long)vn * TT + kb0_ + vkh * 16]); \
    cpa16(Vb_ + (uint32_t)((vn * VSTW + vkh * 8 + 4) * 4), \
          &vg[(long)vn * TT + kb0_ + vkh * 16 + 8]); \
    CP_COMMIT(); \
} while (0)

__global__ void __launch_bounds__(256, 1)
flash_k(const __half* __restrict__ Qh, const __half* __restrict__ Kh,
        const __half* __restrict__ Vt, __half* __restrict__ ctxh)
{
    extern __shared__ uint32_t smw[];
    uint32_t smb = (uint32_t)__cvta_generic_to_shared(smw);

    const int tid = threadIdx.x;
    const int lane = tid & 31;
    const int w = tid >> 5;
    const int quad = lane >> 2;
    const int j = lane & 3;
    const int qt = gridDim.x - 1 - blockIdx.x;
    const int h  = blockIdx.y;
    const int b  = blockIdx.z;
    const int hk = h >> 2;

    const __half* qg = Qh + ((long)(b * NH  + h ) * TT + qt * 128) * HDm;
    const __half* kg = Kh + ((long)(b * NKV + hk) * TT) * HDm;
    const __half* vg = Vt + ((long)(b * NKV + hk) * HDm) * TT;   // [d][t]

    // ---- Phase A: stage Q -> smem, pull frags ----
    for (int i = tid; i < 2048; i += 256) {
        int r = i >> 4, c = i & 15;
        *(uint4*)&smw[r * KSTW + c * 4] = *(const uint4*)&qg[(long)r * HDm + c * 8];
    }
    __syncthreads();

    uint32_t qf[8][4];
    {
        int r = w * 16 + quad;
#pragma unroll
        for (int ks = 0; ks < 8; ks++) {
            int base = ks * 8 + j;
            qf[ks][0] = smw[r * KSTW + base];
            qf[ks][1] = smw[(r + 8) * KSTW + base];
            qf[ks][2] = smw[r * KSTW + base + 4];
            qf[ks][3] = smw[(r + 8) * KSTW + base + 4];
        }
    }
    __syncthreads();

    uint32_t* Ks = smw;
    uint32_t* Vtile = smw + FK_VOFFW;
    uint32_t* Ps = smw + FK_POFFW;

    float oacc[16][4];
#pragma unroll
    for (int nt = 0; nt < 16; nt++)
#pragma unroll
        for (int r = 0; r < 4; r++) oacc[nt][r] = 0.f;

    float m0 = -INFINITY, m1 = -INFINITY, l0 = 0.f, l1 = 0.f;

    const int nkt = 4 * qt + 4;
    const int prow = w * 16 + quad;
    const int qi1 = qt * 128 + prow;
    const int qi2 = qi1 + 8;

    const int kr = tid >> 4, kc = tid & 15;
    const int vn = tid & 127, vkh = tid >> 7;

    FLASH_ISSUE(0);

    for (int kt = 0; kt < nkt; kt++) {
        uint32_t* Kb = Ks + (kt & 1) * 32 * KSTW;
        uint32_t* Vb = Vtile + (kt & 1) * 128 * VSTW;

        CP_WAIT(0);
        __syncthreads();
        if (kt + 1 < nkt) FLASH_ISSUE(kt + 1);

        // ---- S = Q @ K^T (fp16 k16) ----
        float sf[4][4];
#pragma unroll
        for (int nt = 0; nt < 4; nt++)
#pragma unroll
            for (int r = 0; r < 4; r++) sf[nt][r] = 0.f;

#pragma unroll
        for (int ks = 0; ks < 8; ks++) {
#pragma unroll
            for (int nt = 0; nt < 4; nt++) {
                int key = nt * 8 + quad;
                uint32_t b0 = Kb[key * KSTW + ks * 8 + j];
                uint32_t b1 = Kb[key * KSTW + ks * 8 + j + 4];
                mma_f16(sf[nt], qf[ks][0], qf[ks][1], qf[ks][2], qf[ks][3], b0, b1);
            }
        }

        // ---- causal mask ----
        if (kt >= 4 * qt) {
#pragma unroll
            for (int nt = 0; nt < 4; nt++) {
                int kj = kt * 32 + nt * 8 + 2 * j;
                if (kj     > qi1) sf[nt][0] = -INFINITY;
                if (kj + 1 > qi1) sf[nt][1] = -INFINITY;
                if (kj     > qi2) sf[nt][2] = -INFINITY;
                if (kj + 1 > qi2) sf[nt][3] = -INFINITY;
            }
        }

        // ---- online softmax (base 2) ----
        float mx0 = -INFINITY, mx1 = -INFINITY;
#pragma unroll
        for (int nt = 0; nt < 4; nt++) {
            mx0 = fmaxf(mx0, fmaxf(sf[nt][0], sf[nt][1]));
            mx1 = fmaxf(mx1, fmaxf(sf[nt][2], sf[nt][3]));
        }
        mx0 = fmaxf(mx0, __shfl_xor_sync(0xffffffffu, mx0, 1));
        mx0 = fmaxf(mx0, __shfl_xor_sync(0xffffffffu, mx0, 2));
        mx1 = fmaxf(mx1, __shfl_xor_sync(0xffffffffu, mx1, 1));
        mx1 = fmaxf(mx1, __shfl_xor_sync(0xffffffffu, mx1, 2));

        float mn0 = fmaxf(m0, mx0);
        float mn1 = fmaxf(m1, mx1);
        float a0 = ex2(m0 - mn0);
        float a1 = ex2(m1 - mn1);
        m0 = mn0; m1 = mn1;

        float s0 = 0.f, s1 = 0.f;
#pragma unroll
        for (int nt = 0; nt < 4; nt++) {
            float p0 = rhf(ex2(sf[nt][0] - mn0));
            float p1 = rhf(ex2(sf[nt][1] - mn0));
            float p2 = rhf(ex2(sf[nt][2] - mn1));
            float p3 = rhf(ex2(sf[nt][3] - mn1));
            s0 += p0 + p1;
            s1 += p2 + p3;
            Ps[prow * PSTW + nt * 4 + j]       = f2h2(p0, p1);
            Ps[(prow + 8) * PSTW + nt * 4 + j] = f2h2(p2, p3);
        }
        s0 += __shfl_xor_sync(0xffffffffu, s0, 1);
        s0 += __shfl_xor_sync(0xffffffffu, s0, 2);
        s1 += __shfl_xor_sync(0xffffffffu, s1, 1);
        s1 += __shfl_xor_sync(0xffffffffu, s1, 2);
        l0 = l0 * a0 + s0;
        l1 = l1 * a1 + s1;

#pragma unroll
        for (int nt = 0; nt < 16; nt++) {
            oacc[nt][0] *= a0; oacc[nt][1] *= a0;
            oacc[nt][2] *= a1; oacc[nt][3] *= a1;
        }
        __syncwarp();

        // ---- O += P @ V ----
#pragma unroll
        for (int kb = 0; kb < 2; kb++) {
            uint32_t pa0 = Ps[prow * PSTW + kb * 8 + j];
            uint32_t pa1 = Ps[(prow + 8) * PSTW + kb * 8 + j];
            uint32_t pa2 = Ps[prow * PSTW + kb * 8 + j + 4];
            uint32_t pa3 = Ps[(prow + 8) * PSTW + kb * 8 + j + 4];
#pragma unroll
            for (int nt = 0; nt < 16; nt++) {
                int n = nt * 8 + quad;
                uint32_t b0 = Vb[n * VSTW + kb * 8 + j];
                uint32_t b1 = Vb[n * VSTW + kb * 8 + j + 4];
                mma_f16(oacc[nt], pa0, pa1, pa2, pa3, b0, b1);
            }
        }
    }

    // ---- normalize + write fp16 ctx (B,T,D) ----
    float li0 = 1.0f / l0;
    float li1 = 1.0f / l1;
    int t1 = qt * 128 + prow;
    int t2 = t1 + 8;
#pragma unroll
    for (int nt = 0; nt < 16; nt++) {
        int n = h * HDm + nt * 8 + 2 * j;
        *(uint32_t*)&ctxh[((long)(b * TT + t1)) * DD + n] =
            f2h2(oacc[nt][0] * li0, oacc[nt][1] * li0);
        *(uint32_t*)&ctxh[((long)(b * TT + t2)) * DD + n] =
            f2h2(oacc[nt][2] * li1, oacc[nt][3] * li1);
    }
}

// ---------------------------------------------------------------------------
extern "C" void kernel_launch(void* const* d_in, const int* in_sizes, int n_in,
                              void* d_out, int out_size)
{
    const float* x  = (const float*)d_in[0];
    const float* wq = (const float*)d_in[1];
    const float* wk = (const float*)d_in[2];
    const float* wv = (const float*)d_in[3];
    const float* wo = (const float*)d_in[4];
    float* out = (float*)d_out;

    float *q, *k, *v, *tab;
    __half *xh, *wh, *qh, *kh, *vt;
    cudaGetSymbolAddress((void**)&q,   g_q);
    cudaGetSymbolAddress((void**)&k,   g_k);
    cudaGetSymbolAddress((void**)&v,   g_v);
    cudaGetSymbolAddress((void**)&tab, g_rope);
    cudaGetSymbolAddress((void**)&xh,  g_xh);
    cudaGetSymbolAddress((void**)&wh,  g_wh);
    cudaGetSymbolAddress((void**)&qh,  g_qh);
    cudaGetSymbolAddress((void**)&kh,  g_kh);
    cudaGetSymbolAddress((void**)&vt,  g_vt);

    cudaFuncSetAttribute(tqkv_k, cudaFuncAttributeMaxDynamicSharedMemorySize,
                         GEMM_SMEM_BYTES);
    cudaFuncSetAttribute(tgemm_k, cudaFuncAttributeMaxDynamicSharedMemorySize,
                         GEMM_SMEM_BYTES);
    cudaFuncSetAttribute(flash_k, cudaFuncAttributeMaxDynamicSharedMemorySize,
                         FLASH_SMEM_BYTES);

    rope_table_k<<<TT, 64>>>(tab);

    dim3 tb(32, 8);
    wtrans_k<<<dim3(64, 64), tb>>>(wq, 2048, 0,    wh);
    wtrans_k<<<dim3(16, 64), tb>>>(wk, 512,  2048, wh);
    wtrans_k<<<dim3(16, 64), tb>>>(wv, 512,  2560, wh);
    wtrans_k<<<dim3(64, 64), tb>>>(wo, 2048, 3072, wh);
    tohalf_k<<<(MROWS * GK / 4) / 256, 256>>>(x, xh);

    // Fused QKV projection (cp.async pipeline)
    tqkv_k<<<dim3(24, 32), 128, GEMM_SMEM_BYTES>>>(xh, wh, q, k, v);

    // Rope q/k -> fp16; transpose v -> fp16 [d][t]
    ropeh2_k<<<(QROWS + KROWS) / 4, 256>>>(q, k, tab, qh, kh);
    vtrans_k<<<dim3(TT / 32, HDm / 32, BB * NKV), tb>>>(v, vt);

    // Flash attention -> fp16 ctx (into xh)
    flash_k<<<dim3(TT / 128, NH, BB), 256, FLASH_SMEM_BYTES>>>(qh, kh, vt, xh);

    // Output projection
    tgemm_k<<<dim3(16, 32), 128, GEMM_SMEM_BYTES>>>(xh, wh, out);
}

// round 14
// speedup vs baseline: 2.1283x; 1.0582x over previous
#include <cuda_runtime.h>
#include <cuda_fp16.h>
#include <math.h>
#include <stdint.h>

// Problem constants
#define BB   2
#define TT   2048
#define DD   2048
#define NH   16
#define NKV  4
#define HDm  128
#define MROWS (BB*TT)   // 4096
#define GK   2048
#define QROWS (BB*NH*TT)
#define KROWS (BB*NKV*TT)

// Scratch
__device__ float g_q[BB*NH*TT*HDm];
__device__ float g_k[BB*NKV*TT*HDm];
__device__ float g_v[BB*NKV*TT*HDm];
__device__ float g_rope[TT*128];
__device__ __half g_xh[(long)MROWS*GK];          // fp16 activations (x, then attn ctx)
__device__ __half g_wh[5120L*GK];                // fp16 weights^T
__device__ __half g_qh[(long)QROWS*HDm];
__device__ __half g_kh[(long)KROWS*HDm];
__device__ __half g_vt[(long)KROWS*HDm];         // v transposed [bhk][d][t]

// ---------------------------------------------------------------------------
// helpers
// ---------------------------------------------------------------------------
__device__ __forceinline__ uint32_t f2h2(float a, float b) {
    __half2 h = __floats2half2_rn(a, b);
    return *reinterpret_cast<uint32_t*>(&h);
}
__device__ __forceinline__ float rhf(float x) {
    return __half2float(__float2half_rn(x));
}
__device__ __forceinline__ float ex2(float x) {
    float y; asm("ex2.approx.f32 %0, %1;" : "=f"(y) : "f"(x)); return y;
}
__device__ __forceinline__ void mma_f16(float c[4],
                                        uint32_t a0, uint32_t a1, uint32_t a2, uint32_t a3,
                                        uint32_t b0, uint32_t b1) {
    asm volatile(
        "mma.sync.aligned.m16n8k16.row.col.f32.f16.f16.f32 "
        "{%0,%1,%2,%3}, {%4,%5,%6,%7}, {%8,%9}, {%0,%1,%2,%3};\n"
        : "+f"(c[0]), "+f"(c[1]), "+f"(c[2]), "+f"(c[3])
        : "r"(a0), "r"(a1), "r"(a2), "r"(a3), "r"(b0), "r"(b1));
}
__device__ __forceinline__ void cpa16(uint32_t dst, const void* src) {
    asm volatile("cp.async.cg.shared.global [%0], [%1], 16;\n"
                 :: "r"(dst), "l"(src) : "memory");
}
#define CP_COMMIT() asm volatile("cp.async.commit_group;\n" ::: "memory")
#define CP_WAIT(n)  asm volatile("cp.async.wait_group %0;\n" :: "n"(n) : "memory")

// ---------------------------------------------------------------------------
// Prep kernels
// ---------------------------------------------------------------------------
__global__ void wtrans_k(const float* __restrict__ w, int Nw, int nbase,
                         __half* __restrict__ wt)
{
    __shared__ float t[32][33];
    int n0 = blockIdx.x * 32, k0 = blockIdx.y * 32;
#pragma unroll
    for (int i = 0; i < 4; i++)
        t[threadIdx.y + i * 8][threadIdx.x] =
            w[(size_t)(k0 + threadIdx.y + i * 8) * Nw + n0 + threadIdx.x];
    __syncthreads();
#pragma unroll
    for (int i = 0; i < 4; i++) {
        int n = n0 + threadIdx.y + i * 8;
        int k = k0 + threadIdx.x;
        wt[(size_t)(nbase + n) * GK + k] = __float2half(t[threadIdx.x][threadIdx.y + i * 8]);
    }
}

__global__ void tohalf_k(const float* __restrict__ src, __half* __restrict__ dst)
{
    int i = blockIdx.x * blockDim.x + threadIdx.x;
    float4 v = ((const float4*)src)[i];
    ((uint2*)dst)[i] = make_uint2(f2h2(v.x, v.y), f2h2(v.z, v.w));
}

__global__ void rope_table_k(float* __restrict__ tab)
{
    int t = blockIdx.x;
    int j = threadIdx.x;
    float inv = exp2f(-(float)j * (13.287712379549449f / 64.0f));
    float ang = (float)t * inv;
    tab[t * 128 + j]      = cosf(ang);
    tab[t * 128 + 64 + j] = sinf(ang);
}

#define SCALE_LOG2E 0.12751744709274227f
__global__ void ropeh2_k(const float* __restrict__ qp, const float* __restrict__ kp,
                         const float* __restrict__ tab,
                         __half* __restrict__ qh, __half* __restrict__ kh)
{
    int row = blockIdx.x * 4 + (threadIdx.x >> 6);
    int j = threadIdx.x & 63;
    const float* src;
    __half* dst;
    float sc;
    int r;
    if (row < QROWS) { src = qp; dst = qh; r = row;         sc = SCALE_LOG2E; }
    else             { src = kp; dst = kh; r = row - QROWS; sc = 1.0f; }
    int t = r & 2047;
    float c = tab[t * 128 + j];
    float s = tab[t * 128 + 64 + j];
    const float* p = src + (long)r * 128;
    float x1 = p[j], x2 = p[j + 64];
    dst[(long)r * 128 + j]      = __float2half((x1 * c - x2 * s) * sc);
    dst[(long)r * 128 + j + 64] = __float2half((x2 * c + x1 * s) * sc);
}

__global__ void vtrans_k(const float* __restrict__ v, __half* __restrict__ vt)
{
    __shared__ float t[32][33];
    int t0 = blockIdx.x * 32, d0 = blockIdx.y * 32, bhk = blockIdx.z;
    const float* src = v + (size_t)bhk * TT * HDm;
    __half* dst = vt + (size_t)bhk * HDm * TT;
#pragma unroll
    for (int i = 0; i < 4; i++)
        t[threadIdx.y + i * 8][threadIdx.x] =
            src[(size_t)(t0 + threadIdx.y + i * 8) * HDm + d0 + threadIdx.x];
    __syncthreads();
#pragma unroll
    for (int i = 0; i < 4; i++) {
        int d = d0 + threadIdx.y + i * 8;
        dst[(size_t)d * TT + t0 + threadIdx.x] =
            __float2half(t[threadIdx.x][threadIdx.y + i * 8]);
    }
}

// ---------------------------------------------------------------------------
// fp16 GEMM, 3-stage cp.async pipeline: BM=BN=128, BK=32, 128 threads,
// 3 CTAs/SM for latency hiding.
// ---------------------------------------------------------------------------
#define ASTW 20
#define A_SZW (128 * ASTW)
#define GBUFW (2 * A_SZW)                  // 5120 words / stage
#define GEMM_STAGE_BYTES (GBUFW * 4)       // 20480
#define GEMM_SMEM_BYTES (3 * GEMM_STAGE_BYTES)   // 61440

#define GEMM_ISSUE(kt, s) do { \
    uint32_t As_ = smb + (s) * GEMM_STAGE_BYTES; \
    uint32_t Bs_ = As_ + A_SZW * 4; \
    int k0_ = (kt) * 32; \
    _Pragma("unroll") \
    for (int p = 0; p < 4; p++) { \
        cpa16(As_ + (uint32_t)(((srow + p * 32) * ASTW + scolw) * 4), \
              &Ah[(size_t)(m0 + srow + p * 32) * GK + k0_ + scolh]); \
        cpa16(Bs_ + (uint32_t)(((srow + p * 32) * ASTW + scolw) * 4), \
              &Wh[(size_t)(nrow0 + srow + p * 32) * GK + k0_ + scolh]); \
    } \
    CP_COMMIT(); \
} while (0)

__global__ void __launch_bounds__(128, 3)
tqkv_k(const __half* __restrict__ Ah, const __half* __restrict__ Wh,
       float* __restrict__ qo, float* __restrict__ ko, float* __restrict__ vo)
{
    extern __shared__ uint32_t gsm[];
    uint32_t smb = (uint32_t)__cvta_generic_to_shared(gsm);

    const int bx = blockIdx.x;
    float* C;
    int n0, nrow0, Hx;
    if (bx < 16)      { C = qo; n0 = bx * 128;        nrow0 = n0;        Hx = 16; }
    else if (bx < 20) { C = ko; n0 = (bx - 16) * 128; nrow0 = 2048 + n0; Hx = 4;  }
    else              { C = vo; n0 = (bx - 20) * 128; nrow0 = 2560 + n0; Hx = 4;  }

    const int tid = threadIdx.x;
    const int lane = tid & 31;
    const int wid = tid >> 5;
    const int warpM = wid & 1;
    const int warpN = wid >> 1;
    const int m0 = blockIdx.y * 128;

    const int srow = tid >> 2;
    const int scolw = (tid & 3) * 4;
    const int scolh = (tid & 3) * 8;

    float acc[4][8][4];
#pragma unroll
    for (int i = 0; i < 4; i++)
#pragma unroll
        for (int jj = 0; jj < 8; jj++)
#pragma unroll
            for (int r = 0; r < 4; r++) acc[i][jj][r] = 0.f;

    const int NKT = GK / 32;
    GEMM_ISSUE(0, 0);
    GEMM_ISSUE(1, 1);

    for (int kt = 0; kt < NKT; kt++) {
        if (kt + 1 < NKT) { CP_WAIT(1); } else { CP_WAIT(0); }
        __syncthreads();
        uint32_t* As = gsm + (kt % 3) * GBUFW;
        uint32_t* Bs = As + A_SZW;

#pragma unroll
        for (int ks = 0; ks < 2; ks++) {
            const int base = ks * 8 + (lane & 3);
            uint32_t af[4][4];
#pragma unroll
            for (int mi = 0; mi < 4; mi++) {
                int m = warpM * 64 + mi * 16 + (lane >> 2);
                af[mi][0] = As[m * ASTW + base];
                af[mi][1] = As[(m + 8) * ASTW + base];
                af[mi][2] = As[m * ASTW + base + 4];
                af[mi][3] = As[(m + 8) * ASTW + base + 4];
            }
#pragma unroll
            for (int nt = 0; nt < 8; nt++) {
                int n = warpN * 64 + nt * 8 + (lane >> 2);
                uint32_t b0 = Bs[n * ASTW + base];
                uint32_t b1 = Bs[n * ASTW + base + 4];
#pragma unroll
                for (int mi = 0; mi < 4; mi++)
                    mma_f16(acc[mi][nt], af[mi][0], af[mi][1], af[mi][2], af[mi][3], b0, b1);
            }
        }
        if (kt + 2 < NKT) GEMM_ISSUE(kt + 2, (kt + 2) % 3);
    }

#pragma unroll
    for (int mi = 0; mi < 4; mi++) {
        int r1 = m0 + warpM * 64 + mi * 16 + (lane >> 2);
        int r2 = r1 + 8;
#pragma unroll
        for (int nt = 0; nt < 8; nt++) {
            int c = n0 + warpN * 64 + nt * 8 + (lane & 3) * 2;
            int h = c >> 7, d = c & 127;
            int b1 = r1 >> 11, t1 = r1 & 2047;
            int b2 = r2 >> 11, t2 = r2 & 2047;
            *(float2*)&C[((long)(b1 * Hx + h) * TT + t1) * HDm + d] =
                make_float2(acc[mi][nt][0], acc[mi][nt][1]);
            *(float2*)&C[((long)(b2 * Hx + h) * TT + t2) * HDm + d] =
                make_float2(acc[mi][nt][2], acc[mi][nt][3]);
        }
    }
}

__global__ void __launch_bounds__(128, 3)
tgemm_k(const __half* __restrict__ Ah, const __half* __restrict__ Wh,
        float* __restrict__ C)
{
    extern __shared__ uint32_t gsm[];
    uint32_t smb = (uint32_t)__cvta_generic_to_shared(gsm);

    const int tid = threadIdx.x;
    const int lane = tid & 31;
    const int wid = tid >> 5;
    const int warpM = wid & 1;
    const int warpN = wid >> 1;
    const int m0 = blockIdx.y * 128;
    const int n0 = blockIdx.x * 128;
    const int nrow0 = 3072 + n0;

    const int srow = tid >> 2;
    const int scolw = (tid & 3) * 4;
    const int scolh = (tid & 3) * 8;

    float acc[4][8][4];
#pragma unroll
    for (int i = 0; i < 4; i++)
#pragma unroll
        for (int jj = 0; jj < 8; jj++)
#pragma unroll
            for (int r = 0; r < 4; r++) acc[i][jj][r] = 0.f;

    const int NKT = GK / 32;
    GEMM_ISSUE(0, 0);
    GEMM_ISSUE(1, 1);

    for (int kt = 0; kt < NKT; kt++) {
        if (kt + 1 < NKT) { CP_WAIT(1); } else { CP_WAIT(0); }
        __syncthreads();
        uint32_t* As = gsm + (kt % 3) * GBUFW;
        uint32_t* Bs = As + A_SZW;

#pragma unroll
        for (int ks = 0; ks < 2; ks++) {
            const int base = ks * 8 + (lane & 3);
            uint32_t af[4][4];
#pragma unroll
            for (int mi = 0; mi < 4; mi++) {
                int m = warpM * 64 + mi * 16 + (lane >> 2);
                af[mi][0] = As[m * ASTW + base];
                af[mi][1] = As[(m + 8) * ASTW + base];
                af[mi][2] = As[m * ASTW + base + 4];
                af[mi][3] = As[(m + 8) * ASTW + base + 4];
            }
#pragma unroll
            for (int nt = 0; nt < 8; nt++) {
                int n = warpN * 64 + nt * 8 + (lane >> 2);
                uint32_t b0 = Bs[n * ASTW + base];
                uint32_t b1 = Bs[n * ASTW + base + 4];
#pragma unroll
                for (int mi = 0; mi < 4; mi++)
                    mma_f16(acc[mi][nt], af[mi][0], af[mi][1], af[mi][2], af[mi][3], b0, b1);
            }
        }
        if (kt + 2 < NKT) GEMM_ISSUE(kt + 2, (kt + 2) % 3);
    }

#pragma unroll
    for (int mi = 0; mi < 4; mi++) {
        int r1 = m0 + warpM * 64 + mi * 16 + (lane >> 2);
        int r2 = r1 + 8;
#pragma unroll
        for (int nt = 0; nt < 8; nt++) {
            int c = n0 + warpN * 64 + nt * 8 + (lane & 3) * 2;
            *(float2*)&C[(long)r1 * DD + c] = make_float2(acc[mi][nt][0], acc[mi][nt][1]);
            *(float2*)&C[(long)r2 * DD + c] = make_float2(acc[mi][nt][2], acc[mi][nt][3]);
        }
    }
}

// ---------------------------------------------------------------------------
// Causal flash attention: BQ=128, BK=64, 256 threads (8 warps).
// fp16 pre-roped operands, cp.async double-buffered staging, fp16 ctx out.
// K tile: 64 rows x 128 dims (64 words/row, stride KSTW).
// V tile: 128 dims x 64 keys (32 words/row, stride VSTW).
// ---------------------------------------------------------------------------
#define KSTW 68
#define VSTW 36
#define PSTW 36
#define FK_VOFFW (2 * 64 * KSTW)               // 8704
#define FK_POFFW (FK_VOFFW + 2 * 128 * VSTW)   // 17920
#define FLASH_SMEM_WORDS (FK_POFFW + 128 * PSTW)   // 22528
#define FLASH_SMEM_BYTES (FLASH_SMEM_WORDS * 4)    // 90112

#define FLASH_ISSUE(kt) do { \
    uint32_t Kb_ = smb + (uint32_t)(((kt) & 1) * 64 * KSTW * 4); \
    uint32_t Vb_ = smb + (uint32_t)(FK_VOFFW * 4 + ((kt) & 1) * 128 * VSTW * 4); \
    int kb0_ = (kt) * 64; \
    _Pragma("unroll") \
    for (int s = 0; s < 4; s++) { \
        int slot = tid + s * 256; \
        int krow = slot >> 4, kc16 = slot & 15; \
        cpa16(Kb_ + (uint32_t)(krow * (KSTW * 4) + kc16 * 16), \
              &kg[(long)(kb0_ + krow) * HDm + kc16 * 8]); \
    } \
    _Pragma("unroll") \
    for (int s = 0; s < 4; s++) { \
        int slot = tid + s * 256; \
        int vd = slot >> 3, vc16 = slot & 7; \
        cpa16(Vb_ + (uint32_t)(vd * (VSTW * 4) + vc16 * 16), \
              &vg[(long)vd * TT + kb0_ + vc16 * 8]); \
    } \
    CP_COMMIT(); \
} while (0)

__global__ void __launch_bounds__(256, 1)
flash_k(const __half* __restrict__ Qh, const __half* __restrict__ Kh,
        const __half* __restrict__ Vt, __half* __restrict__ ctxh)
{
    extern __shared__ uint32_t smw[];
    uint32_t smb = (uint32_t)__cvta_generic_to_shared(smw);

    const int tid = threadIdx.x;
    const int lane = tid & 31;
    const int w = tid >> 5;
    const int quad = lane >> 2;
    const int j = lane & 3;
    const int qt = gridDim.x - 1 - blockIdx.x;
    const int h  = blockIdx.y;
    const int b  = blockIdx.z;
    const int hk = h >> 2;

    const __half* qg = Qh + ((long)(b * NH  + h ) * TT + qt * 128) * HDm;
    const __half* kg = Kh + ((long)(b * NKV + hk) * TT) * HDm;
    const __half* vg = Vt + ((long)(b * NKV + hk) * HDm) * TT;   // [d][t]

    // ---- Phase A: stage Q -> smem (aliases K region), pull frags ----
    for (int i = tid; i < 2048; i += 256) {
        int r = i >> 4, c = i & 15;
        *(uint4*)&smw[r * KSTW + c * 4] = *(const uint4*)&qg[(long)r * HDm + c * 8];
    }
    __syncthreads();

    uint32_t qf[8][4];
    {
        int r = w * 16 + quad;
#pragma unroll
        for (int ks = 0; ks < 8; ks++) {
            int base = ks * 8 + j;
            qf[ks][0] = smw[r * KSTW + base];
            qf[ks][1] = smw[(r + 8) * KSTW + base];
            qf[ks][2] = smw[r * KSTW + base + 4];
            qf[ks][3] = smw[(r + 8) * KSTW + base + 4];
        }
    }
    __syncthreads();

    uint32_t* Ks = smw;
    uint32_t* Vtile = smw + FK_VOFFW;
    uint32_t* Ps = smw + FK_POFFW;

    float oacc[16][4];
#pragma unroll
    for (int nt = 0; nt < 16; nt++)
#pragma unroll
        for (int r = 0; r < 4; r++) oacc[nt][r] = 0.f;

    float m0 = -INFINITY, m1 = -INFINITY, l0 = 0.f, l1 = 0.f;

    const int nkt = 2 * qt + 2;          // 64-key tiles
    const int prow = w * 16 + quad;
    const int qi1 = qt * 128 + prow;
    const int qi2 = qi1 + 8;

    FLASH_ISSUE(0);

    for (int kt = 0; kt < nkt; kt++) {
        uint32_t* Kb = Ks + (kt & 1) * 64 * KSTW;
        uint32_t* Vb = Vtile + (kt & 1) * 128 * VSTW;

        CP_WAIT(0);
        __syncthreads();
        if (kt + 1 < nkt) FLASH_ISSUE(kt + 1);

        // ---- S = Q @ K^T (128 x 64 per CTA; 16 x 64 per warp) ----
        float sf[8][4];
#pragma unroll
        for (int nt = 0; nt < 8; nt++)
#pragma unroll
            for (int r = 0; r < 4; r++) sf[nt][r] = 0.f;

#pragma unroll
        for (int ks = 0; ks < 8; ks++) {
#pragma unroll
            for (int nt = 0; nt < 8; nt++) {
                int key = nt * 8 + quad;
                uint32_t b0 = Kb[key * KSTW + ks * 8 + j];
                uint32_t b1 = Kb[key * KSTW + ks * 8 + j + 4];
                mma_f16(sf[nt], qf[ks][0], qf[ks][1], qf[ks][2], qf[ks][3], b0, b1);
            }
        }

        // ---- causal mask (last two tiles only) ----
        if (kt >= 2 * qt) {
#pragma unroll
            for (int nt = 0; nt < 8; nt++) {
                int kj = kt * 64 + nt * 8 + 2 * j;
                if (kj     > qi1) sf[nt][0] = -INFINITY;
                if (kj + 1 > qi1) sf[nt][1] = -INFINITY;
                if (kj     > qi2) sf[nt][2] = -INFINITY;
                if (kj + 1 > qi2) sf[nt][3] = -INFINITY;
            }
        }

        // ---- online softmax (base 2), quad reduction ----
        float mx0 = -INFINITY, mx1 = -INFINITY;
#pragma unroll
        for (int nt = 0; nt < 8; nt++) {
            mx0 = fmaxf(mx0, fmaxf(sf[nt][0], sf[nt][1]));
            mx1 = fmaxf(mx1, fmaxf(sf[nt][2], sf[nt][3]));
        }
        mx0 = fmaxf(mx0, __shfl_xor_sync(0xffffffffu, mx0, 1));
        mx0 = fmaxf(mx0, __shfl_xor_sync(0xffffffffu, mx0, 2));
        mx1 = fmaxf(mx1, __shfl_xor_sync(0xffffffffu, mx1, 1));
        mx1 = fmaxf(mx1, __shfl_xor_sync(0xffffffffu, mx1, 2));

        float mn0 = fmaxf(m0, mx0);
        float mn1 = fmaxf(m1, mx1);
        float a0 = ex2(m0 - mn0);
        float a1 = ex2(m1 - mn1);
        m0 = mn0; m1 = mn1;

        float s0 = 0.f, s1 = 0.f;
#pragma unroll
        for (int nt = 0; nt < 8; nt++) {
            float p0 = rhf(ex2(sf[nt][0] - mn0));
            float p1 = rhf(ex2(sf[nt][1] - mn0));
            float p2 = rhf(ex2(sf[nt][2] - mn1));
            float p3 = rhf(ex2(sf[nt][3] - mn1));
            s0 += p0 + p1;
            s1 += p2 + p3;
            Ps[prow * PSTW + nt * 4 + j]       = f2h2(p0, p1);
            Ps[(prow + 8) * PSTW + nt * 4 + j] = f2h2(p2, p3);
        }
        s0 += __shfl_xor_sync(0xffffffffu, s0, 1);
        s0 += __shfl_xor_sync(0xffffffffu, s0, 2);
        s1 += __shfl_xor_sync(0xffffffffu, s1, 1);
        s1 += __shfl_xor_sync(0xffffffffu, s1, 2);
        l0 = l0 * a0 + s0;
        l1 = l1 * a1 + s1;

#pragma unroll
        for (int nt = 0; nt < 16; nt++) {
            oacc[nt][0] *= a0; oacc[nt][1] *= a0;
            oacc[nt][2] *= a1; oacc[nt][3] *= a1;
        }
        __syncwarp();

        // ---- O += P @ V (4 k16 steps over 64 keys) ----
#pragma unroll
        for (int kb = 0; kb < 4; kb++) {
            uint32_t pa0 = Ps[prow * PSTW + kb * 8 + j];
            uint32_t pa1 = Ps[(prow + 8) * PSTW + kb * 8 + j];
            uint32_t pa2 = Ps[prow * PSTW + kb * 8 + j + 4];
            uint32_t pa3 = Ps[(prow + 8) * PSTW + kb * 8 + j + 4];
#pragma unroll
            for (int nt = 0; nt < 16; nt++) {
                int n = nt * 8 + quad;
                uint32_t b0 = Vb[n * VSTW + kb * 8 + j];
                uint32_t b1 = Vb[n * VSTW + kb * 8 + j + 4];
                mma_f16(oacc[nt], pa0, pa1, pa2, pa3, b0, b1);
            }
        }
    }

    // ---- normalize + write fp16 ctx (B,T,D) ----
    float li0 = 1.0f / l0;
    float li1 = 1.0f / l1;
    int t1 = qt * 128 + prow;
    int t2 = t1 + 8;
#pragma unroll
    for (int nt = 0; nt < 16; nt++) {
        int n = h * HDm + nt * 8 + 2 * j;
        *(uint32_t*)&ctxh[((long)(b * TT + t1)) * DD + n] =
            f2h2(oacc[nt][0] * li0, oacc[nt][1] * li0);
        *(uint32_t*)&ctxh[((long)(b * TT + t2)) * DD + n] =
            f2h2(oacc[nt][2] * li1, oacc[nt][3] * li1);
    }
}

// ---------------------------------------------------------------------------
extern "C" void kernel_launch(void* const* d_in, const int* in_sizes, int n_in,
                              void* d_out, int out_size)
{
    const float* x  = (const float*)d_in[0];
    const float* wq = (const float*)d_in[1];
    const float* wk = (const float*)d_in[2];
    const float* wv = (const float*)d_in[3];
    const float* wo = (const float*)d_in[4];
    float* out = (float*)d_out;

    float *q, *k, *v, *tab;
    __half *xh, *wh, *qh, *kh, *vt;
    cudaGetSymbolAddress((void**)&q,   g_q);
    cudaGetSymbolAddress((void**)&k,   g_k);
    cudaGetSymbolAddress((void**)&v,   g_v);
    cudaGetSymbolAddress((void**)&tab, g_rope);
    cudaGetSymbolAddress((void**)&xh,  g_xh);
    cudaGetSymbolAddress((void**)&wh,  g_wh);
    cudaGetSymbolAddress((void**)&qh,  g_qh);
    cudaGetSymbolAddress((void**)&kh,  g_kh);
    cudaGetSymbolAddress((void**)&vt,  g_vt);

    cudaFuncSetAttribute(tqkv_k, cudaFuncAttributeMaxDynamicSharedMemorySize,
                         GEMM_SMEM_BYTES);
    cudaFuncSetAttribute(tgemm_k, cudaFuncAttributeMaxDynamicSharedMemorySize,
                         GEMM_SMEM_BYTES);
    cudaFuncSetAttribute(flash_k, cudaFuncAttributeMaxDynamicSharedMemorySize,
                         FLASH_SMEM_BYTES);

    rope_table_k<<<TT, 64>>>(tab);

    dim3 tb(32, 8);
    wtrans_k<<<dim3(64, 64), tb>>>(wq, 2048, 0,    wh);
    wtrans_k<<<dim3(16, 64), tb>>>(wk, 512,  2048, wh);
    wtrans_k<<<dim3(16, 64), tb>>>(wv, 512,  2560, wh);
    wtrans_k<<<dim3(64, 64), tb>>>(wo, 2048, 3072, wh);
    tohalf_k<<<(MROWS * GK / 4) / 256, 256>>>(x, xh);

    // Fused QKV projection (cp.async pipeline, 3 CTA/SM)
    tqkv_k<<<dim3(24, 32), 128, GEMM_SMEM_BYTES>>>(xh, wh, q, k, v);

    // Rope q/k -> fp16; transpose v -> fp16 [d][t]
    ropeh2_k<<<(QROWS + KROWS) / 4, 256>>>(q, k, tab, qh, kh);
    vtrans_k<<<dim3(TT / 32, HDm / 32, BB * NKV), tb>>>(v, vt);

    // Flash attention (BK=64) -> fp16 ctx (into xh)
    flash_k<<<dim3(TT / 128, NH, BB), 256, FLASH_SMEM_BYTES>>>(qh, kh, vt, xh);

    // Output projection
    tgemm_k<<<dim3(16, 32), 128, GEMM_SMEM_BYTES>>>(xh, wh, out);
}

// round 15
// speedup vs baseline: 2.1663x; 1.0179x over previous
#include <cuda_runtime.h>
#include <cuda_fp16.h>
#include <math.h>
#include <stdint.h>

// Problem constants
#define BB   2
#define TT   2048
#define DD   2048
#define NH   16
#define NKV  4
#define HDm  128
#define MROWS (BB*TT)   // 4096
#define GK   2048
#define QROWS (BB*NH*TT)
#define KROWS (BB*NKV*TT)

// Scratch
__device__ float g_q[BB*NH*TT*HDm];
__device__ float g_k[BB*NKV*TT*HDm];
__device__ float g_v[BB*NKV*TT*HDm];
__device__ float g_rope[TT*128];
__device__ __half g_xh[(long)MROWS*GK];
__device__ __half g_wh[5120L*GK];
__device__ __half g_qh[(long)QROWS*HDm];
__device__ __half g_kh[(long)KROWS*HDm];
__device__ __half g_vt[(long)KROWS*HDm];

// ---------------------------------------------------------------------------
// helpers
// ---------------------------------------------------------------------------
__device__ __forceinline__ uint32_t f2h2(float a, float b) {
    __half2 h = __floats2half2_rn(a, b);
    return *reinterpret_cast<uint32_t*>(&h);
}
__device__ __forceinline__ float rhf(float x) {
    return __half2float(__float2half_rn(x));
}
__device__ __forceinline__ float ex2(float x) {
    float y; asm("ex2.approx.f32 %0, %1;" : "=f"(y) : "f"(x)); return y;
}
__device__ __forceinline__ void mma_f16(float c[4],
                                        uint32_t a0, uint32_t a1, uint32_t a2, uint32_t a3,
                                        uint32_t b0, uint32_t b1) {
    asm volatile(
        "mma.sync.aligned.m16n8k16.row.col.f32.f16.f16.f32 "
        "{%0,%1,%2,%3}, {%4,%5,%6,%7}, {%8,%9}, {%0,%1,%2,%3};\n"
        : "+f"(c[0]), "+f"(c[1]), "+f"(c[2]), "+f"(c[3])
        : "r"(a0), "r"(a1), "r"(a2), "r"(a3), "r"(b0), "r"(b1));
}
__device__ __forceinline__ void ldm_x4(uint32_t& r0, uint32_t& r1,
                                       uint32_t& r2, uint32_t& r3, uint32_t addr) {
    asm volatile("ldmatrix.sync.aligned.m8n8.x4.shared.b16 {%0,%1,%2,%3}, [%4];"
                 : "=r"(r0), "=r"(r1), "=r"(r2), "=r"(r3) : "r"(addr));
}
__device__ __forceinline__ void cpa16(uint32_t dst, const void* src) {
    asm volatile("cp.async.cg.shared.global [%0], [%1], 16;\n"
                 :: "r"(dst), "l"(src) : "memory");
}
#define CP_COMMIT() asm volatile("cp.async.commit_group;\n" ::: "memory")
#define CP_WAIT(n)  asm volatile("cp.async.wait_group %0;\n" :: "n"(n) : "memory")

// ---------------------------------------------------------------------------
// Prep kernels
// ---------------------------------------------------------------------------
__global__ void wtrans_k(const float* __restrict__ w, int Nw, int nbase,
                         __half* __restrict__ wt)
{
    __shared__ float t[32][33];
    int n0 = blockIdx.x * 32, k0 = blockIdx.y * 32;
#pragma unroll
    for (int i = 0; i < 4; i++)
        t[threadIdx.y + i * 8][threadIdx.x] =
            w[(size_t)(k0 + threadIdx.y + i * 8) * Nw + n0 + threadIdx.x];
    __syncthreads();
#pragma unroll
    for (int i = 0; i < 4; i++) {
        int n = n0 + threadIdx.y + i * 8;
        int k = k0 + threadIdx.x;
        wt[(size_t)(nbase + n) * GK + k] = __float2half(t[threadIdx.x][threadIdx.y + i * 8]);
    }
}

__global__ void tohalf_k(const float* __restrict__ src, __half* __restrict__ dst)
{
    int i = blockIdx.x * blockDim.x + threadIdx.x;
    float4 v = ((const float4*)src)[i];
    ((uint2*)dst)[i] = make_uint2(f2h2(v.x, v.y), f2h2(v.z, v.w));
}

__global__ void rope_table_k(float* __restrict__ tab)
{
    int t = blockIdx.x;
    int j = threadIdx.x;
    float inv = exp2f(-(float)j * (13.287712379549449f / 64.0f));
    float ang = (float)t * inv;
    tab[t * 128 + j]      = cosf(ang);
    tab[t * 128 + 64 + j] = sinf(ang);
}

#define SCALE_LOG2E 0.12751744709274227f
__global__ void ropeh2_k(const float* __restrict__ qp, const float* __restrict__ kp,
                         const float* __restrict__ tab,
                         __half* __restrict__ qh, __half* __restrict__ kh)
{
    int row = blockIdx.x * 4 + (threadIdx.x >> 6);
    int j = threadIdx.x & 63;
    const float* src;
    __half* dst;
    float sc;
    int r;
    if (row < QROWS) { src = qp; dst = qh; r = row;         sc = SCALE_LOG2E; }
    else             { src = kp; dst = kh; r = row - QROWS; sc = 1.0f; }
    int t = r & 2047;
    float c = tab[t * 128 + j];
    float s = tab[t * 128 + 64 + j];
    const float* p = src + (long)r * 128;
    float x1 = p[j], x2 = p[j + 64];
    dst[(long)r * 128 + j]      = __float2half((x1 * c - x2 * s) * sc);
    dst[(long)r * 128 + j + 64] = __float2half((x2 * c + x1 * s) * sc);
}

__global__ void vtrans_k(const float* __restrict__ v, __half* __restrict__ vt)
{
    __shared__ float t[32][33];
    int t0 = blockIdx.x * 32, d0 = blockIdx.y * 32, bhk = blockIdx.z;
    const float* src = v + (size_t)bhk * TT * HDm;
    __half* dst = vt + (size_t)bhk * HDm * TT;
#pragma unroll
    for (int i = 0; i < 4; i++)
        t[threadIdx.y + i * 8][threadIdx.x] =
            src[(size_t)(t0 + threadIdx.y + i * 8) * HDm + d0 + threadIdx.x];
    __syncthreads();
#pragma unroll
    for (int i = 0; i < 4; i++) {
        int d = d0 + threadIdx.y + i * 8;
        dst[(size_t)d * TT + t0 + threadIdx.x] =
            __float2half(t[threadIdx.x][threadIdx.y + i * 8]);
    }
}

// ---------------------------------------------------------------------------
// fp16 GEMM, 3-stage cp.async pipeline + ldmatrix fragments.
// BM=BN=128, BK=32, 128 threads, 3 CTAs/SM.
// ---------------------------------------------------------------------------
#define ASTW 20
#define A_SZW (128 * ASTW)
#define GBUFW (2 * A_SZW)
#define GEMM_STAGE_BYTES (GBUFW * 4)
#define GEMM_SMEM_BYTES (3 * GEMM_STAGE_BYTES)

#define GEMM_ISSUE(kt, s) do { \
    uint32_t As_ = smb + (s) * GEMM_STAGE_BYTES; \
    uint32_t Bs_ = As_ + A_SZW * 4; \
    int k0_ = (kt) * 32; \
    _Pragma("unroll") \
    for (int p = 0; p < 4; p++) { \
        cpa16(As_ + (uint32_t)(((srow + p * 32) * ASTW + scolw) * 4), \
              &Ah[(size_t)(m0 + srow + p * 32) * GK + k0_ + scolh]); \
        cpa16(Bs_ + (uint32_t)(((srow + p * 32) * ASTW + scolw) * 4), \
              &Wh[(size_t)(nrow0 + srow + p * 32) * GK + k0_ + scolh]); \
    } \
    CP_COMMIT(); \
} while (0)

// shared compute body for both GEMM kernels
#define GEMM_COMPUTE_TILE(Abase, Bbase) do { \
    _Pragma("unroll") \
    for (int ks = 0; ks < 2; ks++) { \
        uint32_t af[4][4]; \
        _Pragma("unroll") \
        for (int mi = 0; mi < 4; mi++) { \
            int r = warpM * 64 + mi * 16 + lrow + ls8 * 8; \
            ldm_x4(af[mi][0], af[mi][1], af[mi][2], af[mi][3], \
                   (Abase) + (uint32_t)((r * ASTW + ks * 8 + ls16 * 4) * 4)); \
        } \
        _Pragma("unroll") \
        for (int ntp = 0; ntp < 8; ntp += 2) { \
            int n = warpN * 64 + ntp * 8 + lrow + ls16 * 8; \
            uint32_t b00, b01, b10, b11; \
            ldm_x4(b00, b01, b10, b11, \
                   (Bbase) + (uint32_t)((n * ASTW + ks * 8 + ls8 * 4) * 4)); \
            _Pragma("unroll") \
            for (int mi = 0; mi < 4; mi++) { \
                mma_f16(acc[mi][ntp],     af[mi][0], af[mi][1], af[mi][2], af[mi][3], b00, b01); \
                mma_f16(acc[mi][ntp + 1], af[mi][0], af[mi][1], af[mi][2], af[mi][3], b10, b11); \
            } \
        } \
    } \
} while (0)

__global__ void __launch_bounds__(128, 3)
tqkv_k(const __half* __restrict__ Ah, const __half* __restrict__ Wh,
       float* __restrict__ qo, float* __restrict__ ko, float* __restrict__ vo)
{
    extern __shared__ uint32_t gsm[];
    uint32_t smb = (uint32_t)__cvta_generic_to_shared(gsm);

    const int bx = blockIdx.x;
    float* C;
    int n0, nrow0, Hx;
    if (bx < 16)      { C = qo; n0 = bx * 128;        nrow0 = n0;        Hx = 16; }
    else if (bx < 20) { C = ko; n0 = (bx - 16) * 128; nrow0 = 2048 + n0; Hx = 4;  }
    else              { C = vo; n0 = (bx - 20) * 128; nrow0 = 2560 + n0; Hx = 4;  }

    const int tid = threadIdx.x;
    const int lane = tid & 31;
    const int wid = tid >> 5;
    const int warpM = wid & 1;
    const int warpN = wid >> 1;
    const int m0 = blockIdx.y * 128;

    const int srow = tid >> 2;
    const int scolw = (tid & 3) * 4;
    const int scolh = (tid & 3) * 8;
    const int lrow = lane & 7;
    const int ls8 = (lane >> 3) & 1;
    const int ls16 = (lane >> 4) & 1;

    float acc[4][8][4];
#pragma unroll
    for (int i = 0; i < 4; i++)
#pragma unroll
        for (int jj = 0; jj < 8; jj++)
#pragma unroll
            for (int r = 0; r < 4; r++) acc[i][jj][r] = 0.f;

    const int NKT = GK / 32;
    GEMM_ISSUE(0, 0);
    GEMM_ISSUE(1, 1);

    for (int kt = 0; kt < NKT; kt++) {
        if (kt + 1 < NKT) { CP_WAIT(1); } else { CP_WAIT(0); }
        __syncthreads();
        uint32_t Abase = smb + (kt % 3) * GEMM_STAGE_BYTES;
        uint32_t Bbase = Abase + A_SZW * 4;
        GEMM_COMPUTE_TILE(Abase, Bbase);
        if (kt + 2 < NKT) GEMM_ISSUE(kt + 2, (kt + 2) % 3);
    }

#pragma unroll
    for (int mi = 0; mi < 4; mi++) {
        int r1 = m0 + warpM * 64 + mi * 16 + (lane >> 2);
        int r2 = r1 + 8;
#pragma unroll
        for (int nt = 0; nt < 8; nt++) {
            int c = n0 + warpN * 64 + nt * 8 + (lane & 3) * 2;
            int h = c >> 7, d = c & 127;
            int b1 = r1 >> 11, t1 = r1 & 2047;
            int b2 = r2 >> 11, t2 = r2 & 2047;
            *(float2*)&C[((long)(b1 * Hx + h) * TT + t1) * HDm + d] =
                make_float2(acc[mi][nt][0], acc[mi][nt][1]);
            *(float2*)&C[((long)(b2 * Hx + h) * TT + t2) * HDm + d] =
                make_float2(acc[mi][nt][2], acc[mi][nt][3]);
        }
    }
}

__global__ void __launch_bounds__(128, 3)
tgemm_k(const __half* __restrict__ Ah, const __half* __restrict__ Wh,
        float* __restrict__ C)
{
    extern __shared__ uint32_t gsm[];
    uint32_t smb = (uint32_t)__cvta_generic_to_shared(gsm);

    const int tid = threadIdx.x;
    const int lane = tid & 31;
    const int wid = tid >> 5;
    const int warpM = wid & 1;
    const int warpN = wid >> 1;
    const int m0 = blockIdx.y * 128;
    const int n0 = blockIdx.x * 128;
    const int nrow0 = 3072 + n0;

    const int srow = tid >> 2;
    const int scolw = (tid & 3) * 4;
    const int scolh = (tid & 3) * 8;
    const int lrow = lane & 7;
    const int ls8 = (lane >> 3) & 1;
    const int ls16 = (lane >> 4) & 1;

    float acc[4][8][4];
#pragma unroll
    for (int i = 0; i < 4; i++)
#pragma unroll
        for (int jj = 0; jj < 8; jj++)
#pragma unroll
            for (int r = 0; r < 4; r++) acc[i][jj][r] = 0.f;

    const int NKT = GK / 32;
    GEMM_ISSUE(0, 0);
    GEMM_ISSUE(1, 1);

    for (int kt = 0; kt < NKT; kt++) {
        if (kt + 1 < NKT) { CP_WAIT(1); } else { CP_WAIT(0); }
        __syncthreads();
        uint32_t Abase = smb + (kt % 3) * GEMM_STAGE_BYTES;
        uint32_t Bbase = Abase + A_SZW * 4;
        GEMM_COMPUTE_TILE(Abase, Bbase);
        if (kt + 2 < NKT) GEMM_ISSUE(kt + 2, (kt + 2) % 3);
    }

#pragma unroll
    for (int mi = 0; mi < 4; mi++) {
        int r1 = m0 + warpM * 64 + mi * 16 + (lane >> 2);
        int r2 = r1 + 8;
#pragma unroll
        for (int nt = 0; nt < 8; nt++) {
            int c = n0 + warpN * 64 + nt * 8 + (lane & 3) * 2;
            *(float2*)&C[(long)r1 * DD + c] = make_float2(acc[mi][nt][0], acc[mi][nt][1]);
            *(float2*)&C[(long)r2 * DD + c] = make_float2(acc[mi][nt][2], acc[mi][nt][3]);
        }
    }
}

// ---------------------------------------------------------------------------
// Causal flash attention: BQ=128, BK=64, 256 threads, ldmatrix fragments.
// ---------------------------------------------------------------------------
#define KSTW 68
#define VSTW 36
#define PSTW 36
#define FK_VOFFW (2 * 64 * KSTW)               // 8704
#define FK_POFFW (FK_VOFFW + 2 * 128 * VSTW)   // 17920
#define FLASH_SMEM_WORDS (FK_POFFW + 128 * PSTW)   // 22528
#define FLASH_SMEM_BYTES (FLASH_SMEM_WORDS * 4)    // 90112

#define FLASH_ISSUE(kt) do { \
    uint32_t Kb_ = smb + (uint32_t)(((kt) & 1) * 64 * KSTW * 4); \
    uint32_t Vb_ = smb + (uint32_t)(FK_VOFFW * 4 + ((kt) & 1) * 128 * VSTW * 4); \
    int kb0_ = (kt) * 64; \
    _Pragma("unroll") \
    for (int s = 0; s < 4; s++) { \
        int slot = tid + s * 256; \
        int krow = slot >> 4, kc16 = slot & 15; \
        cpa16(Kb_ + (uint32_t)(krow * (KSTW * 4) + kc16 * 16), \
              &kg[(long)(kb0_ + krow) * HDm + kc16 * 8]); \
    } \
    _Pragma("unroll") \
    for (int s = 0; s < 4; s++) { \
        int slot = tid + s * 256; \
        int vd = slot >> 3, vc16 = slot & 7; \
        cpa16(Vb_ + (uint32_t)(vd * (VSTW * 4) + vc16 * 16), \
              &vg[(long)vd * TT + kb0_ + vc16 * 8]); \
    } \
    CP_COMMIT(); \
} while (0)

__global__ void __launch_bounds__(256, 1)
flash_k(const __half* __restrict__ Qh, const __half* __restrict__ Kh,
        const __half* __restrict__ Vt, __half* __restrict__ ctxh)
{
    extern __shared__ uint32_t smw[];
    uint32_t smb = (uint32_t)__cvta_generic_to_shared(smw);

    const int tid = threadIdx.x;
    const int lane = tid & 31;
    const int w = tid >> 5;
    const int quad = lane >> 2;
    const int j = lane & 3;
    const int lrow = lane & 7;
    const int ls8 = (lane >> 3) & 1;
    const int ls16 = (lane >> 4) & 1;
    const int qt = gridDim.x - 1 - blockIdx.x;
    const int h  = blockIdx.y;
    const int b  = blockIdx.z;
    const int hk = h >> 2;

    const __half* qg = Qh + ((long)(b * NH  + h ) * TT + qt * 128) * HDm;
    const __half* kg = Kh + ((long)(b * NKV + hk) * TT) * HDm;
    const __half* vg = Vt + ((long)(b * NKV + hk) * HDm) * TT;   // [d][t]

    // ---- Phase A: stage Q -> smem (aliases K region), pull frags ----
    for (int i = tid; i < 2048; i += 256) {
        int r = i >> 4, c = i & 15;
        *(uint4*)&smw[r * KSTW + c * 4] = *(const uint4*)&qg[(long)r * HDm + c * 8];
    }
    __syncthreads();

    uint32_t qf[8][4];
    {
#pragma unroll
        for (int ks = 0; ks < 8; ks++) {
            int r = w * 16 + lrow + ls8 * 8;
            ldm_x4(qf[ks][0], qf[ks][1], qf[ks][2], qf[ks][3],
                   smb + (uint32_t)((r * KSTW + ks * 8 + ls16 * 4) * 4));
        }
    }
    __syncthreads();

    uint32_t Ps_b = smb + FK_POFFW * 4;
    uint32_t* Ps = smw + FK_POFFW;

    float oacc[16][4];
#pragma unroll
    for (int nt = 0; nt < 16; nt++)
#pragma unroll
        for (int r = 0; r < 4; r++) oacc[nt][r] = 0.f;

    float m0 = -INFINITY, m1 = -INFINITY, l0 = 0.f, l1 = 0.f;

    const int nkt = 2 * qt + 2;
    const int prow = w * 16 + quad;
    const int qi1 = qt * 128 + prow;
    const int qi2 = qi1 + 8;

    FLASH_ISSUE(0);

    for (int kt = 0; kt < nkt; kt++) {
        uint32_t Kb_b = smb + (uint32_t)((kt & 1) * 64 * KSTW * 4);
        uint32_t Vb_b = smb + (uint32_t)(FK_VOFFW * 4 + (kt & 1) * 128 * VSTW * 4);

        CP_WAIT(0);
        __syncthreads();
        if (kt + 1 < nkt) FLASH_ISSUE(kt + 1);

        // ---- S = Q @ K^T ----
        float sf[8][4];
#pragma unroll
        for (int nt = 0; nt < 8; nt++)
#pragma unroll
            for (int r = 0; r < 4; r++) sf[nt][r] = 0.f;

#pragma unroll
        for (int ks = 0; ks < 8; ks++) {
#pragma unroll
            for (int ntp = 0; ntp < 8; ntp += 2) {
                int key = ntp * 8 + lrow + ls16 * 8;
                uint32_t b00, b01, b10, b11;
                ldm_x4(b00, b01, b10, b11,
                       Kb_b + (uint32_t)((key * KSTW + ks * 8 + ls8 * 4) * 4));
                mma_f16(sf[ntp],     qf[ks][0], qf[ks][1], qf[ks][2], qf[ks][3], b00, b01);
                mma_f16(sf[ntp + 1], qf[ks][0], qf[ks][1], qf[ks][2], qf[ks][3], b10, b11);
            }
        }

        // ---- causal mask (last two tiles only) ----
        if (kt >= 2 * qt) {
#pragma unroll
            for (int nt = 0; nt < 8; nt++) {
                int kj = kt * 64 + nt * 8 + 2 * j;
                if (kj     > qi1) sf[nt][0] = -INFINITY;
                if (kj + 1 > qi1) sf[nt][1] = -INFINITY;
                if (kj     > qi2) sf[nt][2] = -INFINITY;
                if (kj + 1 > qi2) sf[nt][3] = -INFINITY;
            }
        }

        // ---- online softmax (base 2), quad reduction ----
        float mx0 = -INFINITY, mx1 = -INFINITY;
#pragma unroll
        for (int nt = 0; nt < 8; nt++) {
            mx0 = fmaxf(mx0, fmaxf(sf[nt][0], sf[nt][1]));
            mx1 = fmaxf(mx1, fmaxf(sf[nt][2], sf[nt][3]));
        }
        mx0 = fmaxf(mx0, __shfl_xor_sync(0xffffffffu, mx0, 1));
        mx0 = fmaxf(mx0, __shfl_xor_sync(0xffffffffu, mx0, 2));
        mx1 = fmaxf(mx1, __shfl_xor_sync(0xffffffffu, mx1, 1));
        mx1 = fmaxf(mx1, __shfl_xor_sync(0xffffffffu, mx1, 2));

        float mn0 = fmaxf(m0, mx0);
        float mn1 = fmaxf(m1, mx1);
        float a0 = ex2(m0 - mn0);
        float a1 = ex2(m1 - mn1);
        m0 = mn0; m1 = mn1;

        float s0 = 0.f, s1 = 0.f;
#pragma unroll
        for (int nt = 0; nt < 8; nt++) {
            float p0 = rhf(ex2(sf[nt][0] - mn0));
            float p1 = rhf(ex2(sf[nt][1] - mn0));
            float p2 = rhf(ex2(sf[nt][2] - mn1));
            float p3 = rhf(ex2(sf[nt][3] - mn1));
            s0 += p0 + p1;
            s1 += p2 + p3;
            Ps[prow * PSTW + nt * 4 + j]       = f2h2(p0, p1);
            Ps[(prow + 8) * PSTW + nt * 4 + j] = f2h2(p2, p3);
        }
        s0 += __shfl_xor_sync(0xffffffffu, s0, 1);
        s0 += __shfl_xor_sync(0xffffffffu, s0, 2);
        s1 += __shfl_xor_sync(0xffffffffu, s1, 1);
        s1 += __shfl_xor_sync(0xffffffffu, s1, 2);
        l0 = l0 * a0 + s0;
        l1 = l1 * a1 + s1;

#pragma unroll
        for (int nt = 0; nt < 16; nt++) {
            oacc[nt][0] *= a0; oacc[nt][1] *= a0;
            oacc[nt][2] *= a1; oacc[nt][3] *= a1;
        }
        __syncwarp();

        // ---- O += P @ V ----
#pragma unroll
        for (int kb = 0; kb < 4; kb++) {
            uint32_t pa0, pa1, pa2, pa3;
            {
                int r = w * 16 + lrow + ls8 * 8;
                ldm_x4(pa0, pa1, pa2, pa3,
                       Ps_b + (uint32_t)((r * PSTW + kb * 8 + ls16 * 4) * 4));
            }
#pragma unroll
            for (int ntp = 0; ntp < 16; ntp += 2) {
                int n = ntp * 8 + lrow + ls16 * 8;
                uint32_t b00, b01, b10, b11;
                ldm_x4(b00, b01, b10, b11,
                       Vb_b + (uint32_t)((n * VSTW + kb * 8 + ls8 * 4) * 4));
                mma_f16(oacc[ntp],     pa0, pa1, pa2, pa3, b00, b01);
                mma_f16(oacc[ntp + 1], pa0, pa1, pa2, pa3, b10, b11);
            }
        }
    }

    // ---- normalize + write fp16 ctx (B,T,D) ----
    float li0 = 1.0f / l0;
    float li1 = 1.0f / l1;
    int t1 = qt * 128 + prow;
    int t2 = t1 + 8;
#pragma unroll
    for (int nt = 0; nt < 16; nt++) {
        int n = h * HDm + nt * 8 + 2 * j;
        *(uint32_t*)&ctxh[((long)(b * TT + t1)) * DD + n] =
            f2h2(oacc[nt][0] * li0, oacc[nt][1] * li0);
        *(uint32_t*)&ctxh[((long)(b * TT + t2)) * DD + n] =
            f2h2(oacc[nt][2] * li1, oacc[nt][3] * li1);
    }
}

// ---------------------------------------------------------------------------
extern "C" void kernel_launch(void* const* d_in, const int* in_sizes, int n_in,
                              void* d_out, int out_size)
{
    const float* x  = (const float*)d_in[0];
    const float* wq = (const float*)d_in[1];
    const float* wk = (const float*)d_in[2];
    const float* wv = (const float*)d_in[3];
    const float* wo = (const float*)d_in[4];
    float* out = (float*)d_out;

    float *q, *k, *v, *tab;
    __half *xh, *wh, *qh, *kh, *vt;
    cudaGetSymbolAddress((void**)&q,   g_q);
    cudaGetSymbolAddress((void**)&k,   g_k);
    cudaGetSymbolAddress((void**)&v,   g_v);
    cudaGetSymbolAddress((void**)&tab, g_rope);
    cudaGetSymbolAddress((void**)&xh,  g_xh);
    cudaGetSymbolAddress((void**)&wh,  g_wh);
    cudaGetSymbolAddress((void**)&qh,  g_qh);
    cudaGetSymbolAddress((void**)&kh,  g_kh);
    cudaGetSymbolAddress((void**)&vt,  g_vt);

    cudaFuncSetAttribute(tqkv_k, cudaFuncAttributeMaxDynamicSharedMemorySize,
                         GEMM_SMEM_BYTES);
    cudaFuncSetAttribute(tgemm_k, cudaFuncAttributeMaxDynamicSharedMemorySize,
                         GEMM_SMEM_BYTES);
    cudaFuncSetAttribute(flash_k, cudaFuncAttributeMaxDynamicSharedMemorySize,
                         FLASH_SMEM_BYTES);

    rope_table_k<<<TT, 64>>>(tab);

    dim3 tb(32, 8);
    wtrans_k<<<dim3(64, 64), tb>>>(wq, 2048, 0,    wh);
    wtrans_k<<<dim3(16, 64), tb>>>(wk, 512,  2048, wh);
    wtrans_k<<<dim3(16, 64), tb>>>(wv, 512,  2560, wh);
    wtrans_k<<<dim3(64, 64), tb>>>(wo, 2048, 3072, wh);
    tohalf_k<<<(MROWS * GK / 4) / 256, 256>>>(x, xh);

    tqkv_k<<<dim3(24, 32), 128, GEMM_SMEM_BYTES>>>(xh, wh, q, k, v);

    ropeh2_k<<<(QROWS + KROWS) / 4, 256>>>(q, k, tab, qh, kh);
    vtrans_k<<<dim3(TT / 32, HDm / 32, BB * NKV), tb>>>(v, vt);

    flash_k<<<dim3(TT / 128, NH, BB), 256, FLASH_SMEM_BYTES>>>(qh, kh, vt, xh);

    tgemm_k<<<dim3(16, 32), 128, GEMM_SMEM_BYTES>>>(xh, wh, out);
}